// round 5
// baseline (speedup 1.0000x reference)
#include <cuda_runtime.h>
#include <cuda_bf16.h>

#define BATCH 8
#define NSEQ  2048
#define DIM   256
#define NROWS (BATCH * NSEQ)          // 16384
#define NEGV  (-999999.0f)

// ---------------- scratch (device globals; no allocation allowed) ----------
__device__ float g_h[(size_t)NROWS * DIM];              // h = X @ W   (16.8 MB)
__device__ __nv_bfloat16 g_hT_hi[(size_t)NROWS * DIM];  // h^T split hi [b][d][j]
__device__ __nv_bfloat16 g_hT_lo[(size_t)NROWS * DIM];  // h^T split lo [b][d][j]
__device__ float g_asrc[NROWS];
__device__ float g_adst[NROWS];
__device__ float g_rowmax[NROWS];
__device__ float g_rowsum[NROWS];
__device__ float g_colpart[BATCH * 64 * DIM];           // partial col-sums of h

__device__ __forceinline__ float fsigmoid(float x) {
    return __fdividef(1.0f, 1.0f + __expf(-x));
}

__device__ __forceinline__ unsigned smem_u32(const void* p) {
    unsigned a;
    asm("{ .reg .u64 t; cvta.to.shared.u64 t, %1; cvt.u32.u64 %0, t; }"
        : "=r"(a) : "l"(p));
    return a;
}

__device__ __forceinline__ void ldsm_x4(unsigned r[4], unsigned addr) {
    asm volatile("ldmatrix.sync.aligned.m8n8.x4.shared.b16 {%0,%1,%2,%3}, [%4];"
                 : "=r"(r[0]), "=r"(r[1]), "=r"(r[2]), "=r"(r[3]) : "r"(addr));
}

__device__ __forceinline__ void mma_bf16(float c[4], const unsigned a[4],
                                         unsigned b0, unsigned b1) {
    asm volatile("mma.sync.aligned.m16n8k16.row.col.f32.bf16.bf16.f32 "
                 "{%0,%1,%2,%3}, {%4,%5,%6,%7}, {%8,%9}, {%0,%1,%2,%3};"
                 : "+f"(c[0]), "+f"(c[1]), "+f"(c[2]), "+f"(c[3])
                 : "r"(a[0]), "r"(a[1]), "r"(a[2]), "r"(a[3]), "r"(b0), "r"(b1));
}

// ---------------- K1: h = X @ W   (NN GEMM, M=16384, N=256, K=256) ---------
__global__ __launch_bounds__(256) void k1_h_gemm(const float* __restrict__ X,
                                                 const float* __restrict__ W)
{
    __shared__ float As[16][65];   // [k][m]
    __shared__ float Bs[16][64];   // [k][n]
    const int t  = threadIdx.x;
    const int tx = t & 15, ty = t >> 4;
    const int m0 = blockIdx.y * 64, n0 = blockIdx.x * 64;
    float acc[4][4] = {};
    for (int k0 = 0; k0 < DIM; k0 += 16) {
        {
            int r = t >> 2, c4 = t & 3;
            float4 v = *(const float4*)(X + (size_t)(m0 + r) * DIM + k0 + c4 * 4);
            As[c4*4+0][r] = v.x; As[c4*4+1][r] = v.y;
            As[c4*4+2][r] = v.z; As[c4*4+3][r] = v.w;
        }
        {
            int r = t >> 4, c4 = t & 15;
            *(float4*)&Bs[r][c4*4] = *(const float4*)(W + (size_t)(k0 + r) * DIM + n0 + c4 * 4);
        }
        __syncthreads();
        #pragma unroll
        for (int k = 0; k < 16; k++) {
            float a[4], bb[4];
            #pragma unroll
            for (int r = 0; r < 4; r++) a[r] = As[k][ty*4 + r];
            *(float4*)bb = *(float4*)&Bs[k][tx*4];
            #pragma unroll
            for (int r = 0; r < 4; r++)
                #pragma unroll
                for (int c = 0; c < 4; c++)
                    acc[r][c] = fmaf(a[r], bb[c], acc[r][c]);
        }
        __syncthreads();
    }
    #pragma unroll
    for (int r = 0; r < 4; r++) {
        float4 v = make_float4(acc[r][0], acc[r][1], acc[r][2], acc[r][3]);
        *(float4*)&g_h[(size_t)(m0 + ty*4 + r) * DIM + n0 + tx*4] = v;
    }
}

// ---------------- K2: a_src / a_dst ------------------------------------------
__global__ __launch_bounds__(256) void k2_coef(const float* __restrict__ Ws)
{
    const int r = blockIdx.x;
    const int t = threadIdx.x;
    float hv = g_h[(size_t)r * DIM + t];
    float ps = hv * Ws[t];
    float pd = hv * Ws[DIM + t];
    __shared__ float ss[8], sd[8];
    #pragma unroll
    for (int o = 16; o > 0; o >>= 1) {
        ps += __shfl_down_sync(0xffffffffu, ps, o);
        pd += __shfl_down_sync(0xffffffffu, pd, o);
    }
    if ((t & 31) == 0) { ss[t >> 5] = ps; sd[t >> 5] = pd; }
    __syncthreads();
    if (t == 0) {
        float a = 0.f, d = 0.f;
        #pragma unroll
        for (int w = 0; w < 8; w++) { a += ss[w]; d += sd[w]; }
        g_asrc[r] = a;
        g_adst[r] = d;
    }
}

// ---------------- K2b: transpose + bf16 split  h -> hT_hi/lo [b][d][j] ------
__global__ __launch_bounds__(256) void k2b_split()
{
    __shared__ float tile[32][33];
    const int b = blockIdx.z, j0 = blockIdx.x * 32, d0 = blockIdx.y * 32;
    const int c = threadIdx.x & 31, r0 = threadIdx.x >> 5;
    #pragma unroll
    for (int k = 0; k < 4; k++) {
        int r = r0 + k * 8;
        tile[r][c] = g_h[((size_t)(b * NSEQ + j0 + r)) * DIM + d0 + c];
    }
    __syncthreads();
    #pragma unroll
    for (int k = 0; k < 4; k++) {
        int r = r0 + k * 8;           // d offset within tile
        float v = tile[c][r];
        __nv_bfloat16 hb = __float2bfloat16_rn(v);
        float hf = __bfloat162float(hb);
        __nv_bfloat16 lb = __float2bfloat16_rn(v - hf);
        size_t o = ((size_t)(b * DIM + d0 + r)) * NSEQ + j0 + c;
        g_hT_hi[o] = hb;
        g_hT_lo[o] = lb;
    }
}

// ---------------- K2c: partial column sums of h (for degenerate rows) -------
__global__ __launch_bounds__(256) void k2c_colpart()
{
    const int p = blockIdx.x;     // 0..63 (j segment of 32)
    const int b = blockIdx.y;
    const int d = threadIdx.x;
    float s = 0.f;
    const float* base = g_h + ((size_t)b * NSEQ + p * 32) * DIM + d;
    #pragma unroll 8
    for (int j = 0; j < 32; j++) s += base[(size_t)j * DIM];
    g_colpart[(b * 64 + p) * DIM + d] = s;
}

// ---------------- K3: write I_A, compute per-row softmax max/sum ------------
__global__ __launch_bounds__(256) void k3_ia_stats(const int*   __restrict__ adj,
                                                   const float* __restrict__ bsv,
                                                   float*       __restrict__ outIA)
{
    const int i = blockIdx.x;
    const int b = blockIdx.y;
    const int t = threadIdx.x;
    const size_t rbase = ((size_t)b * NSEQ + i) * NSEQ;
    const float asrc = g_asrc[b * NSEQ + i];
    const float bs0  = bsv[0];

    float sc[8];
    float mx = -3.0e38f;
    #pragma unroll
    for (int p = 0; p < 8; p++) {
        int j = t + p * 256;
        int av = adj[rbase + j];
        float x = asrc + g_adst[b * NSEQ + j] + bs0;
        float attn = (j < i) ? fsigmoid(x) : 0.0f;
        float ia = ((j == i) ? 1.0f : 0.0f) - attn;
        outIA[rbase + j] = ia;                       // I_A_raw: NOT adj-masked
        float s = ((j <= i) && (av == 1)) ? ia : NEGV;
        sc[p] = s;
        mx = fmaxf(mx, s);
    }
    __shared__ float redm[8], reds[8];
    #pragma unroll
    for (int o = 16; o > 0; o >>= 1) mx = fmaxf(mx, __shfl_xor_sync(0xffffffffu, mx, o));
    if ((t & 31) == 0) redm[t >> 5] = mx;
    __syncthreads();
    float bm = redm[0];
    #pragma unroll
    for (int w = 1; w < 8; w++) bm = fmaxf(bm, redm[w]);

    float sum = 0.f;
    #pragma unroll
    for (int p = 0; p < 8; p++) sum += __expf(sc[p] - bm);
    #pragma unroll
    for (int o = 16; o > 0; o >>= 1) sum += __shfl_xor_sync(0xffffffffu, sum, o);
    if ((t & 31) == 0) reds[t >> 5] = sum;
    __syncthreads();
    if (t == 0) {
        float s = 0.f;
        #pragma unroll
        for (int w = 0; w < 8; w++) s += reds[w];
        g_rowmax[b * NSEQ + i] = bm;
        g_rowsum[b * NSEQ + i] = s;
    }
}

// ---------------- K4: feat_out = P @ h + b, paired-triangular mma.sync ------
// CTA p handles i-block 31-p then i-block p (33 chunks total, uniform).
// Per block: M=64, N=256 (full D), K-chunks 0..bi. 8 warps = 2(m) x 4(n),
// warp tile m32 x n64. SMEM rows pitched 144B.
#define KCH    64
#define PITCHB 144
__global__ __launch_bounds__(256) void k4_mma(const int*   __restrict__ adj,
                                              const float* __restrict__ bias,
                                              const float* __restrict__ bsv,
                                              float*       __restrict__ outFO)
{
    extern __shared__ char sm[];
    // A_hi @0 (9216), A_lo @9216, B_hi @18432 (36864), B_lo @55296 (36864)
    __shared__ float s_asrc[64], s_m[64], s_inv[64], s_adst[KCH];

    const int t    = threadIdx.x;
    const int lane = t & 31;
    const int wid  = t >> 5;
    const int wm   = wid & 1;
    const int wn   = wid >> 1;
    const int pidx = blockIdx.x;            // 0..15
    const int b    = blockIdx.y;

    char* sA_hi = sm;
    char* sA_lo = sm + 9216;
    char* sB_hi = sm + 18432;
    char* sB_lo = sm + 55296;

    const float bs0 = bsv[0];

    const unsigned lrow = (lane & 15);
    const unsigned lcol = (lane >> 4) << 4;
    const unsigned aBase0 = smem_u32(sA_hi) + (wm * 32 + lrow) * PITCHB + lcol;
    const unsigned bBase0 = smem_u32(sB_hi) + (wn * 64 + lrow) * PITCHB + lcol;

    const int pii = t >> 2;
    const int pjq = (t & 3) << 4;

    #pragma unroll
    for (int half = 0; half < 2; half++) {
        const int bi = half ? pidx : (31 - pidx);
        const int i0 = bi * 64;

        if (t < 64) {                       // stats for this block (sync inside loop)
            int r = b * NSEQ + i0 + t;
            s_asrc[t] = g_asrc[r];
            s_m[t]    = g_rowmax[r];
            s_inv[t]  = __fdividef(1.0f, g_rowsum[r]);
        }

        float acc[2][8][4] = {};

        for (int c = 0; c <= bi; c++) {
            const int j0 = c * KCH;
            __syncthreads();                 // prev mma/stats visible
            if (t < KCH) s_adst[t] = g_adst[b * NSEQ + j0 + t];
            __syncthreads();

            // ---- P tile 64x64 -> bf16 hi/lo into sA ----
            {
                const int i = i0 + pii;
                const float asrc = s_asrc[pii], m = s_m[pii], inv = s_inv[pii];
                const int* arow = adj + ((size_t)(b * NSEQ + i)) * NSEQ + j0 + pjq;
                #pragma unroll
                for (int hh = 0; hh < 2; hh++) {
                    int4 a0 = ((const int4*)arow)[hh * 2 + 0];
                    int4 a1 = ((const int4*)arow)[hh * 2 + 1];
                    int av[8] = {a0.x, a0.y, a0.z, a0.w, a1.x, a1.y, a1.z, a1.w};
                    union { __nv_bfloat16 h[8]; uint4 v; } Uh, Ul;
                    #pragma unroll
                    for (int e = 0; e < 8; e++) {
                        const int jl = pjq + hh * 8 + e;
                        const int j  = j0 + jl;
                        float x = asrc + s_adst[jl] + bs0;
                        float attn = (j < i) ? fsigmoid(x) : 0.0f;
                        float ia = ((j == i) ? 1.0f : 0.0f) - attn;
                        float sc = ((j <= i) && (av[e] == 1)) ? ia : NEGV;
                        float pv = __expf(sc - m) * inv;
                        __nv_bfloat16 hb = __float2bfloat16_rn(pv);
                        Uh.h[e] = hb;
                        Ul.h[e] = __float2bfloat16_rn(pv - __bfloat162float(hb));
                    }
                    const unsigned off = pii * PITCHB + (pjq + hh * 8) * 2;
                    *(uint4*)(sA_hi + off) = Uh.v;
                    *(uint4*)(sA_lo + off) = Ul.v;
                }
            }

            // ---- B tile: h^T 256 x 64 hi/lo ----
            #pragma unroll
            for (int q = 0; q < 8; q++) {
                const int idx = q * 256 + t;
                const int d = idx >> 3, seg = idx & 7;
                const size_t go = ((size_t)(b * DIM + d)) * NSEQ + j0 + seg * 8;
                const unsigned off = d * PITCHB + seg * 16;
                *(uint4*)(sB_hi + off) = *(const uint4*)(g_hT_hi + go);
                *(uint4*)(sB_lo + off) = *(const uint4*)(g_hT_lo + go);
            }
            __syncthreads();

            // ---- mma mainloop over 4 k-steps ----
            #pragma unroll
            for (int ks = 0; ks < 4; ks++) {
                unsigned ah[2][4], al[2][4];
                #pragma unroll
                for (int mt = 0; mt < 2; mt++) {
                    ldsm_x4(ah[mt], aBase0 + mt * 16 * PITCHB + ks * 32);
                    ldsm_x4(al[mt], aBase0 + 9216u + mt * 16 * PITCHB + ks * 32);
                }
                #pragma unroll
                for (int np = 0; np < 4; np++) {
                    unsigned bh[4], bl[4];
                    ldsm_x4(bh, bBase0 + np * 16 * PITCHB + ks * 32);
                    ldsm_x4(bl, bBase0 + 36864u + np * 16 * PITCHB + ks * 32);
                    #pragma unroll
                    for (int mt = 0; mt < 2; mt++) {
                        mma_bf16(acc[mt][np*2+0], ah[mt], bh[0], bh[2]);   // hi*hi
                        mma_bf16(acc[mt][np*2+1], ah[mt], bh[1], bh[3]);
                        mma_bf16(acc[mt][np*2+0], ah[mt], bl[0], bl[2]);   // hi*lo
                        mma_bf16(acc[mt][np*2+1], ah[mt], bl[1], bl[3]);
                        mma_bf16(acc[mt][np*2+0], al[mt], bh[0], bh[2]);   // lo*hi
                        mma_bf16(acc[mt][np*2+1], al[mt], bh[1], bh[3]);
                    }
                }
            }
        }

        // ---- epilogue: accum + bias -> outFO ----
        #pragma unroll
        for (int mt = 0; mt < 2; mt++) {
            const int row0 = i0 + wm * 32 + mt * 16 + (lane >> 2);
            #pragma unroll
            for (int nf = 0; nf < 8; nf++) {
                const int col = wn * 64 + nf * 8 + (lane & 3) * 2;
                const float b0 = bias[col], b1 = bias[col + 1];
                float2 v0 = make_float2(acc[mt][nf][0] + b0, acc[mt][nf][1] + b1);
                float2 v1 = make_float2(acc[mt][nf][2] + b0, acc[mt][nf][3] + b1);
                *(float2*)(outFO + ((size_t)(b * NSEQ + row0)) * DIM + col) = v0;
                *(float2*)(outFO + ((size_t)(b * NSEQ + row0 + 8)) * DIM + col) = v1;
            }
        }
        __syncthreads();    // epilogue done before next half's stats overwrite
    }
}

// ---------------- K4fix: degenerate (all-NEG) rows -> uniform softmax -------
__global__ __launch_bounds__(256) void k4fix(const float* __restrict__ bias,
                                             float*       __restrict__ outFO)
{
    const int row = blockIdx.x * 256 + threadIdx.x;
    if (g_rowmax[row] != NEGV) return;          // bit-exact: set iff no allowed entry
    const int b = row >> 11;
    const float inv = __fdividef(1.0f, g_rowsum[row]);   // = 1/2048
    float* orow = outFO + (size_t)row * DIM;
    for (int d = 0; d < DIM; d++) {
        float s = 0.f;
        #pragma unroll
        for (int p = 0; p < 64; p++) s += g_colpart[(b * 64 + p) * DIM + d];
        orow[d] = s * inv + bias[d];
    }
}

// ---------------- K5: gate GEMM (NT) + elu + blend, in-place on d_out -------
__global__ __launch_bounds__(256) void k5_gate(const float* __restrict__ X,
                                               const float* __restrict__ Hw,
                                               const float* __restrict__ Hb,
                                               float*       __restrict__ out)
{
    __shared__ float As[16][65];
    __shared__ float Bs[16][65];
    const int t  = threadIdx.x;
    const int tx = t & 15, ty = t >> 4;
    const int m0 = blockIdx.y * 64, n0 = blockIdx.x * 64;
    float acc[4][4] = {};
    for (int k0 = 0; k0 < DIM; k0 += 16) {
        {
            int r = t >> 2, c4 = t & 3;
            float4 v = *(const float4*)(X + (size_t)(m0 + r) * DIM + k0 + c4 * 4);
            As[c4*4+0][r] = v.x; As[c4*4+1][r] = v.y;
            As[c4*4+2][r] = v.z; As[c4*4+3][r] = v.w;
            float4 w = *(const float4*)(Hw + (size_t)(n0 + r) * DIM + k0 + c4 * 4);
            Bs[c4*4+0][r] = w.x; Bs[c4*4+1][r] = w.y;
            Bs[c4*4+2][r] = w.z; Bs[c4*4+3][r] = w.w;
        }
        __syncthreads();
        #pragma unroll
        for (int k = 0; k < 16; k++) {
            float a[4], bb[4];
            #pragma unroll
            for (int r = 0; r < 4; r++) a[r] = As[k][ty*4 + r];
            #pragma unroll
            for (int c = 0; c < 4; c++) bb[c] = Bs[k][tx*4 + c];
            #pragma unroll
            for (int r = 0; r < 4; r++)
                #pragma unroll
                for (int c = 0; c < 4; c++)
                    acc[r][c] = fmaf(a[r], bb[c], acc[r][c]);
        }
        __syncthreads();
    }
    #pragma unroll
    for (int r = 0; r < 4; r++) {
        int row = m0 + ty*4 + r;
        #pragma unroll
        for (int c = 0; c < 4; c++) {
            int col = n0 + tx*4 + c;
            size_t o = (size_t)row * DIM + col;
            float g  = fsigmoid(acc[r][c] + Hb[col]);
            float fo = out[o];
            float e  = (fo > 0.0f) ? fo : expm1f(fo);
            out[o] = g * e + (1.0f - g) * X[o];
        }
    }
}

// ---------------- launch ----------------------------------------------------
extern "C" void kernel_launch(void* const* d_in, const int* in_sizes, int n_in,
                              void* d_out, int out_size)
{
    const float* feat = (const float*)d_in[0];
    const int*   adj  = (const int*)  d_in[1];
    const float* W    = (const float*)d_in[2];
    const float* bvec = (const float*)d_in[3];
    const float* Ws   = (const float*)d_in[4];
    const float* bs   = (const float*)d_in[5];
    const float* Hw   = (const float*)d_in[6];
    const float* Hb   = (const float*)d_in[7];

    float* out   = (float*)d_out;                      // (B,N,256)
    float* outIA = out + (size_t)NROWS * DIM;          // (B,1,N,N)

    cudaFuncSetAttribute(k4_mma, cudaFuncAttributeMaxDynamicSharedMemorySize, 92160);

    k1_h_gemm<<<dim3(DIM / 64, NROWS / 64), 256>>>(feat, W);
    k2_coef  <<<NROWS, 256>>>(Ws);
    k2b_split<<<dim3(NSEQ / 32, DIM / 32, BATCH), 256>>>();
    k2c_colpart<<<dim3(64, BATCH), 256>>>();
    k3_ia_stats<<<dim3(NSEQ, BATCH), 256>>>(adj, bs, outIA);
    k4_mma   <<<dim3(16, BATCH), 256, 92160>>>(adj, bvec, bs, out);
    k4fix    <<<NROWS / 256, 256>>>(bvec, out);
    k5_gate  <<<dim3(DIM / 64, NROWS / 64), 256>>>(feat, Hw, Hb, out);
}

// round 7
// speedup vs baseline: 1.3462x; 1.3462x over previous
#include <cuda_runtime.h>
#include <cuda_bf16.h>

#define BATCH 8
#define NSEQ  2048
#define DIM   256
#define NROWS (BATCH * NSEQ)          // 16384
#define NEGV  (-999999.0f)

// ---------------- scratch (device globals; no allocation allowed) ----------
__device__ float g_h[(size_t)NROWS * DIM];              // h = X @ W   (16.8 MB)
__device__ __nv_bfloat16 g_hT_hi[(size_t)NROWS * DIM];  // h^T split hi [b][d][j]
__device__ __nv_bfloat16 g_hT_lo[(size_t)NROWS * DIM];  // h^T split lo [b][d][j]
__device__ __nv_bfloat16 g_X_hi[(size_t)NROWS * DIM];   // feat split  [m][k]
__device__ __nv_bfloat16 g_X_lo[(size_t)NROWS * DIM];
__device__ __nv_bfloat16 g_WT_hi[DIM * DIM];            // W^T split   [n][k]
__device__ __nv_bfloat16 g_WT_lo[DIM * DIM];
__device__ __nv_bfloat16 g_Hw_hi[DIM * DIM];            // Hw split    [n][k]
__device__ __nv_bfloat16 g_Hw_lo[DIM * DIM];
__device__ float g_asrc[NROWS];
__device__ float g_adst[NROWS];
__device__ float g_rowmax[NROWS];
__device__ float g_rowsum[NROWS];

__device__ __forceinline__ float fsigmoid(float x) {
    return __fdividef(1.0f, 1.0f + __expf(-x));
}

__device__ __forceinline__ unsigned smem_u32(const void* p) {
    unsigned a;
    asm("{ .reg .u64 t; cvta.to.shared.u64 t, %1; cvt.u32.u64 %0, t; }"
        : "=r"(a) : "l"(p));
    return a;
}

__device__ __forceinline__ void ldsm_x4(unsigned r[4], unsigned addr) {
    asm volatile("ldmatrix.sync.aligned.m8n8.x4.shared.b16 {%0,%1,%2,%3}, [%4];"
                 : "=r"(r[0]), "=r"(r[1]), "=r"(r[2]), "=r"(r[3]) : "r"(addr));
}

__device__ __forceinline__ void mma_bf16(float c[4], const unsigned a[4],
                                         unsigned b0, unsigned b1) {
    asm volatile("mma.sync.aligned.m16n8k16.row.col.f32.bf16.bf16.f32 "
                 "{%0,%1,%2,%3}, {%4,%5,%6,%7}, {%8,%9}, {%0,%1,%2,%3};"
                 : "+f"(c[0]), "+f"(c[1]), "+f"(c[2]), "+f"(c[3])
                 : "r"(a[0]), "r"(a[1]), "r"(a[2]), "r"(a[3]), "r"(b0), "r"(b1));
}

__device__ __forceinline__ void split_bf16(float v, __nv_bfloat16& hi, __nv_bfloat16& lo) {
    hi = __float2bfloat16_rn(v);
    lo = __float2bfloat16_rn(v - __bfloat162float(hi));
}

#define PITCHB 144

// ---------------- K0a: split X (feat) into bf16 hi/lo -----------------------
__global__ __launch_bounds__(256) void k0a_splitX(const float* __restrict__ X)
{
    const size_t base = (size_t)blockIdx.x * 1024 + threadIdx.x * 4;
    float4 v = *(const float4*)(X + base);
    union { __nv_bfloat16 h[4]; uint2 u; } Uh, Ul;
    split_bf16(v.x, Uh.h[0], Ul.h[0]);
    split_bf16(v.y, Uh.h[1], Ul.h[1]);
    split_bf16(v.z, Uh.h[2], Ul.h[2]);
    split_bf16(v.w, Uh.h[3], Ul.h[3]);
    *(uint2*)(g_X_hi + base) = Uh.u;
    *(uint2*)(g_X_lo + base) = Ul.u;
}

// ---------------- K0b: W^T split + Hw split ---------------------------------
__global__ __launch_bounds__(256) void k0b_splitW(const float* __restrict__ W,
                                                  const float* __restrict__ Hw)
{
    const int n = blockIdx.x;            // 0..255
    const int k = threadIdx.x;           // 0..255
    split_bf16(W[k * DIM + n], g_WT_hi[n * DIM + k], g_WT_lo[n * DIM + k]);
    split_bf16(Hw[n * DIM + k], g_Hw_hi[n * DIM + k], g_Hw_lo[n * DIM + k]);
}

// ---------------- K1: h = X @ W via mma.sync bf16 split ---------------------
// CTA: M=64, N=256, K=256 (4 chunks of 64). Writes g_h directly (NO host-passed
// device-global pointer — that was the R6 silent-corruption bug).
__global__ __launch_bounds__(256, 2) void k1_mma()
{
    extern __shared__ char sm[];
    char* sA_hi = sm;
    char* sA_lo = sm + 9216;
    char* sB_hi = sm + 18432;
    char* sB_lo = sm + 55296;

    const int t    = threadIdx.x;
    const int lane = t & 31;
    const int wid  = t >> 5;
    const int wm   = wid & 1;
    const int wn   = wid >> 1;
    const int m0   = blockIdx.x * 64;

    const unsigned lrow = (lane & 15);
    const unsigned lcol = (lane >> 4) << 4;
    const unsigned aBase0 = smem_u32(sA_hi) + (wm * 32 + lrow) * PITCHB + lcol;
    const unsigned bBase0 = smem_u32(sB_hi) + (wn * 64 + lrow) * PITCHB + lcol;

    float acc[2][8][4] = {};

    for (int kc = 0; kc < 4; kc++) {
        const int j0 = kc * 64;
        __syncthreads();
        // A tile 64x64 hi/lo
        #pragma unroll
        for (int q = 0; q < 2; q++) {
            const int idx = q * 256 + t;
            const int row = idx >> 3, seg = idx & 7;
            const size_t go = (size_t)(m0 + row) * DIM + j0 + seg * 8;
            const unsigned off = row * PITCHB + seg * 16;
            *(uint4*)(sA_hi + off) = *(const uint4*)(g_X_hi + go);
            *(uint4*)(sA_lo + off) = *(const uint4*)(g_X_lo + go);
        }
        // B tile 256x64 hi/lo
        #pragma unroll
        for (int q = 0; q < 8; q++) {
            const int idx = q * 256 + t;
            const int d = idx >> 3, seg = idx & 7;
            const size_t go = (size_t)d * DIM + j0 + seg * 8;
            const unsigned off = d * PITCHB + seg * 16;
            *(uint4*)(sB_hi + off) = *(const uint4*)(g_WT_hi + go);
            *(uint4*)(sB_lo + off) = *(const uint4*)(g_WT_lo + go);
        }
        __syncthreads();
        #pragma unroll
        for (int ks = 0; ks < 4; ks++) {
            unsigned ah[2][4], al[2][4];
            #pragma unroll
            for (int mt = 0; mt < 2; mt++) {
                ldsm_x4(ah[mt], aBase0 + mt * 16 * PITCHB + ks * 32);
                ldsm_x4(al[mt], aBase0 + 9216u + mt * 16 * PITCHB + ks * 32);
            }
            #pragma unroll
            for (int np = 0; np < 4; np++) {
                unsigned bh[4], bl[4];
                ldsm_x4(bh, bBase0 + np * 16 * PITCHB + ks * 32);
                ldsm_x4(bl, bBase0 + 36864u + np * 16 * PITCHB + ks * 32);
                #pragma unroll
                for (int mt = 0; mt < 2; mt++) {
                    mma_bf16(acc[mt][np*2+0], ah[mt], bh[0], bh[2]);
                    mma_bf16(acc[mt][np*2+1], ah[mt], bh[1], bh[3]);
                    mma_bf16(acc[mt][np*2+0], ah[mt], bl[0], bl[2]);
                    mma_bf16(acc[mt][np*2+1], ah[mt], bl[1], bl[3]);
                    mma_bf16(acc[mt][np*2+0], al[mt], bh[0], bh[2]);
                    mma_bf16(acc[mt][np*2+1], al[mt], bh[1], bh[3]);
                }
            }
        }
    }
    #pragma unroll
    for (int mt = 0; mt < 2; mt++) {
        const int row0 = m0 + wm * 32 + mt * 16 + (lane >> 2);
        #pragma unroll
        for (int nf = 0; nf < 8; nf++) {
            const int col = wn * 64 + nf * 8 + (lane & 3) * 2;
            *(float2*)(g_h + (size_t)row0 * DIM + col) =
                make_float2(acc[mt][nf][0], acc[mt][nf][1]);
            *(float2*)(g_h + (size_t)(row0 + 8) * DIM + col) =
                make_float2(acc[mt][nf][2], acc[mt][nf][3]);
        }
    }
}

// ---------------- K2: a_src / a_dst ------------------------------------------
__global__ __launch_bounds__(256) void k2_coef(const float* __restrict__ Ws)
{
    const int r = blockIdx.x;
    const int t = threadIdx.x;
    float hv = g_h[(size_t)r * DIM + t];
    float ps = hv * Ws[t];
    float pd = hv * Ws[DIM + t];
    __shared__ float ss[8], sd[8];
    #pragma unroll
    for (int o = 16; o > 0; o >>= 1) {
        ps += __shfl_down_sync(0xffffffffu, ps, o);
        pd += __shfl_down_sync(0xffffffffu, pd, o);
    }
    if ((t & 31) == 0) { ss[t >> 5] = ps; sd[t >> 5] = pd; }
    __syncthreads();
    if (t == 0) {
        float a = 0.f, d = 0.f;
        #pragma unroll
        for (int w = 0; w < 8; w++) { a += ss[w]; d += sd[w]; }
        g_asrc[r] = a;
        g_adst[r] = d;
    }
}

// ---------------- K2b: transpose + bf16 split  h -> hT_hi/lo [b][d][j] ------
__global__ __launch_bounds__(256) void k2b_split()
{
    __shared__ float tile[32][33];
    const int b = blockIdx.z, j0 = blockIdx.x * 32, d0 = blockIdx.y * 32;
    const int c = threadIdx.x & 31, r0 = threadIdx.x >> 5;
    #pragma unroll
    for (int k = 0; k < 4; k++) {
        int r = r0 + k * 8;
        tile[r][c] = g_h[((size_t)(b * NSEQ + j0 + r)) * DIM + d0 + c];
    }
    __syncthreads();
    #pragma unroll
    for (int k = 0; k < 4; k++) {
        int r = r0 + k * 8;           // d offset within tile
        float v = tile[c][r];
        __nv_bfloat16 hb, lb;
        split_bf16(v, hb, lb);
        size_t o = ((size_t)(b * DIM + d0 + r)) * NSEQ + j0 + c;
        g_hT_hi[o] = hb;
        g_hT_lo[o] = lb;
    }
}

// ---------------- K3: write I_A, compute per-row softmax max/sum ------------
__global__ __launch_bounds__(256) void k3_ia_stats(const int*   __restrict__ adj,
                                                   const float* __restrict__ bsv,
                                                   float*       __restrict__ outIA)
{
    const int i = blockIdx.x;
    const int b = blockIdx.y;
    const int t = threadIdx.x;
    const size_t rbase = ((size_t)b * NSEQ + i) * NSEQ;
    const float asrc = g_asrc[b * NSEQ + i];
    const float bs0  = bsv[0];

    float sc[8];
    float mx = -3.0e38f;
    #pragma unroll
    for (int p = 0; p < 8; p++) {
        int j = t + p * 256;
        int av = adj[rbase + j];
        float x = asrc + g_adst[b * NSEQ + j] + bs0;
        float attn = (j < i) ? fsigmoid(x) : 0.0f;
        float ia = ((j == i) ? 1.0f : 0.0f) - attn;
        outIA[rbase + j] = ia;                       // I_A_raw: NOT adj-masked
        float s = ((j <= i) && (av == 1)) ? ia : NEGV;
        sc[p] = s;
        mx = fmaxf(mx, s);
    }
    __shared__ float redm[8], reds[8];
    #pragma unroll
    for (int o = 16; o > 0; o >>= 1) mx = fmaxf(mx, __shfl_xor_sync(0xffffffffu, mx, o));
    if ((t & 31) == 0) redm[t >> 5] = mx;
    __syncthreads();
    float bm = redm[0];
    #pragma unroll
    for (int w = 1; w < 8; w++) bm = fmaxf(bm, redm[w]);

    float sum = 0.f;
    #pragma unroll
    for (int p = 0; p < 8; p++) sum += __expf(sc[p] - bm);   // all-NEG row -> exp(0)=1
    #pragma unroll
    for (int o = 16; o > 0; o >>= 1) sum += __shfl_xor_sync(0xffffffffu, sum, o);
    if ((t & 31) == 0) reds[t >> 5] = sum;
    __syncthreads();
    if (t == 0) {
        float s = 0.f;
        #pragma unroll
        for (int w = 0; w < 8; w++) s += reds[w];
        g_rowmax[b * NSEQ + i] = bm;
        g_rowsum[b * NSEQ + i] = s;
    }
}

// ---------------- K4: feat_out = P @ h + b via mma.sync (full square) -------
// CTA: M=64 (i), N=256 (d), K-chunks of 64 (j). 8 warps = 2(m) x 4(n).
#define KCH 64
__global__ __launch_bounds__(256, 2) void k4_mma(const int*   __restrict__ adj,
                                                 const float* __restrict__ bias,
                                                 const float* __restrict__ bsv,
                                                 float*       __restrict__ outFO)
{
    extern __shared__ char sm[];
    __shared__ float s_asrc[64], s_m[64], s_inv[64], s_adst[KCH];

    const int t    = threadIdx.x;
    const int lane = t & 31;
    const int wid  = t >> 5;
    const int wm   = wid & 1;
    const int wn   = wid >> 1;
    const int b    = blockIdx.y;
    const int i0   = blockIdx.x * 64;

    char* sA_hi = sm;
    char* sA_lo = sm + 9216;
    char* sB_hi = sm + 18432;
    char* sB_lo = sm + 55296;

    if (t < 64) {
        int r = b * NSEQ + i0 + t;
        s_asrc[t] = g_asrc[r];
        s_m[t]    = g_rowmax[r];
        s_inv[t]  = __fdividef(1.0f, g_rowsum[r]);
    }
    const float bs0 = bsv[0];

    const unsigned lrow = (lane & 15);
    const unsigned lcol = (lane >> 4) << 4;
    const unsigned aBase0 = smem_u32(sA_hi) + (wm * 32 + lrow) * PITCHB + lcol;
    const unsigned bBase0 = smem_u32(sB_hi) + (wn * 64 + lrow) * PITCHB + lcol;

    const int pii = t >> 2;
    const int pjq = (t & 3) << 4;

    float acc[2][8][4] = {};

    for (int c = 0; c < NSEQ / KCH; c++) {
        const int j0 = c * KCH;
        __syncthreads();                 // previous chunk's mma done
        if (t < KCH) s_adst[t] = g_adst[b * NSEQ + j0 + t];
        __syncthreads();

        // ---- B tile first: h^T 256 x 64 hi/lo (LDG issues early, overlaps P) ----
        #pragma unroll
        for (int q = 0; q < 8; q++) {
            const int idx = q * 256 + t;
            const int d = idx >> 3, seg = idx & 7;
            const size_t go = ((size_t)(b * DIM + d)) * NSEQ + j0 + seg * 8;
            const unsigned off = d * PITCHB + seg * 16;
            *(uint4*)(sB_hi + off) = *(const uint4*)(g_hT_hi + go);
            *(uint4*)(sB_lo + off) = *(const uint4*)(g_hT_lo + go);
        }

        // ---- P tile 64x64 -> bf16 hi/lo into sA ----
        {
            const int i = i0 + pii;
            const float asrc = s_asrc[pii], m = s_m[pii], inv = s_inv[pii];
            const int* arow = adj + ((size_t)(b * NSEQ + i)) * NSEQ + j0 + pjq;
            #pragma unroll
            for (int half = 0; half < 2; half++) {
                int4 a0 = ((const int4*)arow)[half * 2 + 0];
                int4 a1 = ((const int4*)arow)[half * 2 + 1];
                int av[8] = {a0.x, a0.y, a0.z, a0.w, a1.x, a1.y, a1.z, a1.w};
                union { __nv_bfloat16 h[8]; uint4 v; } Uh, Ul;
                #pragma unroll
                for (int e = 0; e < 8; e++) {
                    const int jl = pjq + half * 8 + e;
                    const int j  = j0 + jl;
                    float x = asrc + s_adst[jl] + bs0;
                    float attn = (j < i) ? fsigmoid(x) : 0.0f;
                    float ia = ((j == i) ? 1.0f : 0.0f) - attn;
                    float sc = ((j <= i) && (av[e] == 1)) ? ia : NEGV;
                    float pv = __expf(sc - m) * inv;
                    __nv_bfloat16 hb, lb;
                    split_bf16(pv, hb, lb);
                    Uh.h[e] = hb;
                    Ul.h[e] = lb;
                }
                const unsigned off = pii * PITCHB + (pjq + half * 8) * 2;
                *(uint4*)(sA_hi + off) = Uh.v;
                *(uint4*)(sA_lo + off) = Ul.v;
            }
        }
        __syncthreads();

        // ---- mma mainloop over 4 k-steps ----
        #pragma unroll
        for (int ks = 0; ks < 4; ks++) {
            unsigned ah[2][4], al[2][4];
            #pragma unroll
            for (int mt = 0; mt < 2; mt++) {
                ldsm_x4(ah[mt], aBase0 + mt * 16 * PITCHB + ks * 32);
                ldsm_x4(al[mt], aBase0 + 9216u + mt * 16 * PITCHB + ks * 32);
            }
            #pragma unroll
            for (int np = 0; np < 4; np++) {
                unsigned bh[4], bl[4];
                ldsm_x4(bh, bBase0 + np * 16 * PITCHB + ks * 32);
                ldsm_x4(bl, bBase0 + 36864u + np * 16 * PITCHB + ks * 32);
                #pragma unroll
                for (int mt = 0; mt < 2; mt++) {
                    mma_bf16(acc[mt][np*2+0], ah[mt], bh[0], bh[2]);   // hi*hi
                    mma_bf16(acc[mt][np*2+1], ah[mt], bh[1], bh[3]);
                    mma_bf16(acc[mt][np*2+0], ah[mt], bl[0], bl[2]);   // hi*lo
                    mma_bf16(acc[mt][np*2+1], ah[mt], bl[1], bl[3]);
                    mma_bf16(acc[mt][np*2+0], al[mt], bh[0], bh[2]);   // lo*hi
                    mma_bf16(acc[mt][np*2+1], al[mt], bh[1], bh[3]);
                }
            }
        }
    }

    // ---- epilogue: accum + bias -> outFO ----
    #pragma unroll
    for (int mt = 0; mt < 2; mt++) {
        const int row0 = i0 + wm * 32 + mt * 16 + (lane >> 2);
        #pragma unroll
        for (int nf = 0; nf < 8; nf++) {
            const int col = wn * 64 + nf * 8 + (lane & 3) * 2;
            const float b0 = bias[col], b1 = bias[col + 1];
            float2 v0 = make_float2(acc[mt][nf][0] + b0, acc[mt][nf][1] + b1);
            float2 v1 = make_float2(acc[mt][nf][2] + b0, acc[mt][nf][3] + b1);
            *(float2*)(outFO + ((size_t)(b * NSEQ + row0)) * DIM + col) = v0;
            *(float2*)(outFO + ((size_t)(b * NSEQ + row0 + 8)) * DIM + col) = v1;
        }
    }
}

// ---------------- K5: gate = sigmoid(X@Hw^T+Hb), blend, via mma.sync --------
__global__ __launch_bounds__(256, 2) void k5_mma(const float* __restrict__ X,
                                                 const float* __restrict__ Hb,
                                                 float*       __restrict__ out)
{
    extern __shared__ char sm[];
    char* sA_hi = sm;
    char* sA_lo = sm + 9216;
    char* sB_hi = sm + 18432;
    char* sB_lo = sm + 55296;

    const int t    = threadIdx.x;
    const int lane = t & 31;
    const int wid  = t >> 5;
    const int wm   = wid & 1;
    const int wn   = wid >> 1;
    const int m0   = blockIdx.x * 64;

    const unsigned lrow = (lane & 15);
    const unsigned lcol = (lane >> 4) << 4;
    const unsigned aBase0 = smem_u32(sA_hi) + (wm * 32 + lrow) * PITCHB + lcol;
    const unsigned bBase0 = smem_u32(sB_hi) + (wn * 64 + lrow) * PITCHB + lcol;

    float acc[2][8][4] = {};

    for (int kc = 0; kc < 4; kc++) {
        const int j0 = kc * 64;
        __syncthreads();
        #pragma unroll
        for (int q = 0; q < 2; q++) {
            const int idx = q * 256 + t;
            const int row = idx >> 3, seg = idx & 7;
            const size_t go = (size_t)(m0 + row) * DIM + j0 + seg * 8;
            const unsigned off = row * PITCHB + seg * 16;
            *(uint4*)(sA_hi + off) = *(const uint4*)(g_X_hi + go);
            *(uint4*)(sA_lo + off) = *(const uint4*)(g_X_lo + go);
        }
        #pragma unroll
        for (int q = 0; q < 8; q++) {
            const int idx = q * 256 + t;
            const int d = idx >> 3, seg = idx & 7;
            const size_t go = (size_t)d * DIM + j0 + seg * 8;
            const unsigned off = d * PITCHB + seg * 16;
            *(uint4*)(sB_hi + off) = *(const uint4*)(g_Hw_hi + go);
            *(uint4*)(sB_lo + off) = *(const uint4*)(g_Hw_lo + go);
        }
        __syncthreads();
        #pragma unroll
        for (int ks = 0; ks < 4; ks++) {
            unsigned ah[2][4], al[2][4];
            #pragma unroll
            for (int mt = 0; mt < 2; mt++) {
                ldsm_x4(ah[mt], aBase0 + mt * 16 * PITCHB + ks * 32);
                ldsm_x4(al[mt], aBase0 + 9216u + mt * 16 * PITCHB + ks * 32);
            }
            #pragma unroll
            for (int np = 0; np < 4; np++) {
                unsigned bh[4], bl[4];
                ldsm_x4(bh, bBase0 + np * 16 * PITCHB + ks * 32);
                ldsm_x4(bl, bBase0 + 36864u + np * 16 * PITCHB + ks * 32);
                #pragma unroll
                for (int mt = 0; mt < 2; mt++) {
                    mma_bf16(acc[mt][np*2+0], ah[mt], bh[0], bh[2]);
                    mma_bf16(acc[mt][np*2+1], ah[mt], bh[1], bh[3]);
                    mma_bf16(acc[mt][np*2+0], ah[mt], bl[0], bl[2]);
                    mma_bf16(acc[mt][np*2+1], ah[mt], bl[1], bl[3]);
                    mma_bf16(acc[mt][np*2+0], al[mt], bh[0], bh[2]);
                    mma_bf16(acc[mt][np*2+1], al[mt], bh[1], bh[3]);
                }
            }
        }
    }

    // epilogue: gate + elu + blend (out holds feat_out pre-activation)
    #pragma unroll
    for (int mt = 0; mt < 2; mt++) {
        const int row0 = m0 + wm * 32 + mt * 16 + (lane >> 2);
        #pragma unroll
        for (int nf = 0; nf < 8; nf++) {
            const int col = wn * 64 + nf * 8 + (lane & 3) * 2;
            const float hb0 = Hb[col], hb1 = Hb[col + 1];
            #pragma unroll
            for (int rr = 0; rr < 2; rr++) {
                const size_t o = (size_t)(row0 + rr * 8) * DIM + col;
                float2 fo = *(const float2*)(out + o);
                float2 xv = *(const float2*)(X + o);
                float g0 = fsigmoid(acc[mt][nf][rr*2+0] + hb0);
                float g1 = fsigmoid(acc[mt][nf][rr*2+1] + hb1);
                float e0 = (fo.x > 0.0f) ? fo.x : expm1f(fo.x);
                float e1 = (fo.y > 0.0f) ? fo.y : expm1f(fo.y);
                float2 r;
                r.x = g0 * e0 + (1.0f - g0) * xv.x;
                r.y = g1 * e1 + (1.0f - g1) * xv.y;
                *(float2*)(out + o) = r;
            }
        }
    }
}

// ---------------- launch ----------------------------------------------------
extern "C" void kernel_launch(void* const* d_in, const int* in_sizes, int n_in,
                              void* d_out, int out_size)
{
    const float* feat = (const float*)d_in[0];
    const int*   adj  = (const int*)  d_in[1];
    const float* W    = (const float*)d_in[2];
    const float* bvec = (const float*)d_in[3];
    const float* Ws   = (const float*)d_in[4];
    const float* bs   = (const float*)d_in[5];
    const float* Hw   = (const float*)d_in[6];
    const float* Hb   = (const float*)d_in[7];

    float* out   = (float*)d_out;                      // (B,N,256)
    float* outIA = out + (size_t)NROWS * DIM;          // (B,1,N,N)

    cudaFuncSetAttribute(k1_mma, cudaFuncAttributeMaxDynamicSharedMemorySize, 92160);
    cudaFuncSetAttribute(k4_mma, cudaFuncAttributeMaxDynamicSharedMemorySize, 92160);
    cudaFuncSetAttribute(k5_mma, cudaFuncAttributeMaxDynamicSharedMemorySize, 92160);

    k0a_splitX<<<NROWS * DIM / 1024, 256>>>(feat);
    k0b_splitW<<<DIM, DIM>>>(W, Hw);
    k1_mma   <<<NROWS / 64, 256, 92160>>>();
    k2_coef  <<<NROWS, 256>>>(Ws);
    k2b_split<<<dim3(NSEQ / 32, DIM / 32, BATCH), 256>>>();
    k3_ia_stats<<<dim3(NSEQ, BATCH), 256>>>(adj, bs, outIA);
    k4_mma   <<<dim3(NSEQ / 64, BATCH), 256, 92160>>>(adj, bvec, bs, out);
    k5_mma   <<<NROWS / 64, 256, 92160>>>(feat, Hb, out);
}

// round 8
// speedup vs baseline: 1.5524x; 1.1531x over previous
#include <cuda_runtime.h>
#include <cuda_bf16.h>

#define BATCH 8
#define NSEQ  2048
#define DIM   256
#define NROWS (BATCH * NSEQ)          // 16384
#define NEGV  (-999999.0f)

// ---------------- scratch (device globals; no allocation allowed) ----------
__device__ float g_h[(size_t)NROWS * DIM];              // h = X @ W   (16.8 MB)
__device__ __nv_bfloat16 g_hT_hi[(size_t)NROWS * DIM];  // h^T split hi [b][d][j]
__device__ __nv_bfloat16 g_hT_lo[(size_t)NROWS * DIM];  // h^T split lo [b][d][j]
__device__ __nv_bfloat16 g_X_hi[(size_t)NROWS * DIM];   // feat split  [m][k]
__device__ __nv_bfloat16 g_X_lo[(size_t)NROWS * DIM];
__device__ __nv_bfloat16 g_WT_hi[DIM * DIM];            // W^T split   [n][k]
__device__ __nv_bfloat16 g_WT_lo[DIM * DIM];
__device__ __nv_bfloat16 g_Hw_hi[DIM * DIM];            // Hw split    [n][k]
__device__ __nv_bfloat16 g_Hw_lo[DIM * DIM];
__device__ __nv_bfloat16 g_P_hi[(size_t)NROWS * NSEQ];  // softmax P split (67MB)
__device__ __nv_bfloat16 g_P_lo[(size_t)NROWS * NSEQ];
__device__ float g_asrc[NROWS];
__device__ float g_adst[NROWS];

__device__ __forceinline__ float fsigmoid(float x) {
    return __fdividef(1.0f, 1.0f + __expf(-x));
}

__device__ __forceinline__ unsigned smem_u32(const void* p) {
    unsigned a;
    asm("{ .reg .u64 t; cvta.to.shared.u64 t, %1; cvt.u32.u64 %0, t; }"
        : "=r"(a) : "l"(p));
    return a;
}

__device__ __forceinline__ void ldsm_x4(unsigned r[4], unsigned addr) {
    asm volatile("ldmatrix.sync.aligned.m8n8.x4.shared.b16 {%0,%1,%2,%3}, [%4];"
                 : "=r"(r[0]), "=r"(r[1]), "=r"(r[2]), "=r"(r[3]) : "r"(addr));
}

__device__ __forceinline__ void mma_bf16(float c[4], const unsigned a[4],
                                         unsigned b0, unsigned b1) {
    asm volatile("mma.sync.aligned.m16n8k16.row.col.f32.bf16.bf16.f32 "
                 "{%0,%1,%2,%3}, {%4,%5,%6,%7}, {%8,%9}, {%0,%1,%2,%3};"
                 : "+f"(c[0]), "+f"(c[1]), "+f"(c[2]), "+f"(c[3])
                 : "r"(a[0]), "r"(a[1]), "r"(a[2]), "r"(a[3]), "r"(b0), "r"(b1));
}

__device__ __forceinline__ void split_bf16(float v, __nv_bfloat16& hi, __nv_bfloat16& lo) {
    hi = __float2bfloat16_rn(v);
    lo = __float2bfloat16_rn(v - __bfloat162float(hi));
}

#define PITCHB 144

// ---------------- K0a: split X (feat) into bf16 hi/lo -----------------------
__global__ __launch_bounds__(256) void k0a_splitX(const float* __restrict__ X)
{
    const size_t base = (size_t)blockIdx.x * 1024 + threadIdx.x * 4;
    float4 v = *(const float4*)(X + base);
    union { __nv_bfloat16 h[4]; uint2 u; } Uh, Ul;
    split_bf16(v.x, Uh.h[0], Ul.h[0]);
    split_bf16(v.y, Uh.h[1], Ul.h[1]);
    split_bf16(v.z, Uh.h[2], Ul.h[2]);
    split_bf16(v.w, Uh.h[3], Ul.h[3]);
    *(uint2*)(g_X_hi + base) = Uh.u;
    *(uint2*)(g_X_lo + base) = Ul.u;
}

// ---------------- K0b: W^T split + Hw split ---------------------------------
__global__ __launch_bounds__(256) void k0b_splitW(const float* __restrict__ W,
                                                  const float* __restrict__ Hw)
{
    const int n = blockIdx.x;            // 0..255
    const int k = threadIdx.x;           // 0..255
    split_bf16(W[k * DIM + n], g_WT_hi[n * DIM + k], g_WT_lo[n * DIM + k]);
    split_bf16(Hw[n * DIM + k], g_Hw_hi[n * DIM + k], g_Hw_lo[n * DIM + k]);
}

// ---------------- K1: h = X @ W via mma.sync bf16 split ---------------------
__global__ __launch_bounds__(256, 2) void k1_mma()
{
    extern __shared__ char sm[];
    char* sA_hi = sm;
    char* sA_lo = sm + 9216;
    char* sB_hi = sm + 18432;
    char* sB_lo = sm + 55296;

    const int t    = threadIdx.x;
    const int lane = t & 31;
    const int wid  = t >> 5;
    const int wm   = wid & 1;
    const int wn   = wid >> 1;
    const int m0   = blockIdx.x * 64;

    const unsigned lrow = (lane & 15);
    const unsigned lcol = (lane >> 4) << 4;
    const unsigned aBase0 = smem_u32(sA_hi) + (wm * 32 + lrow) * PITCHB + lcol;
    const unsigned bBase0 = smem_u32(sB_hi) + (wn * 64 + lrow) * PITCHB + lcol;

    float acc[2][8][4] = {};

    for (int kc = 0; kc < 4; kc++) {
        const int j0 = kc * 64;
        __syncthreads();
        #pragma unroll
        for (int q = 0; q < 2; q++) {
            const int idx = q * 256 + t;
            const int row = idx >> 3, seg = idx & 7;
            const size_t go = (size_t)(m0 + row) * DIM + j0 + seg * 8;
            const unsigned off = row * PITCHB + seg * 16;
            *(uint4*)(sA_hi + off) = *(const uint4*)(g_X_hi + go);
            *(uint4*)(sA_lo + off) = *(const uint4*)(g_X_lo + go);
        }
        #pragma unroll
        for (int q = 0; q < 8; q++) {
            const int idx = q * 256 + t;
            const int d = idx >> 3, seg = idx & 7;
            const size_t go = (size_t)d * DIM + j0 + seg * 8;
            const unsigned off = d * PITCHB + seg * 16;
            *(uint4*)(sB_hi + off) = *(const uint4*)(g_WT_hi + go);
            *(uint4*)(sB_lo + off) = *(const uint4*)(g_WT_lo + go);
        }
        __syncthreads();
        #pragma unroll
        for (int ks = 0; ks < 4; ks++) {
            unsigned ah[2][4], al[2][4];
            #pragma unroll
            for (int mt = 0; mt < 2; mt++) {
                ldsm_x4(ah[mt], aBase0 + mt * 16 * PITCHB + ks * 32);
                ldsm_x4(al[mt], aBase0 + 9216u + mt * 16 * PITCHB + ks * 32);
            }
            #pragma unroll
            for (int np = 0; np < 4; np++) {
                unsigned bh[4], bl[4];
                ldsm_x4(bh, bBase0 + np * 16 * PITCHB + ks * 32);
                ldsm_x4(bl, bBase0 + 36864u + np * 16 * PITCHB + ks * 32);
                #pragma unroll
                for (int mt = 0; mt < 2; mt++) {
                    mma_bf16(acc[mt][np*2+0], ah[mt], bh[0], bh[2]);
                    mma_bf16(acc[mt][np*2+1], ah[mt], bh[1], bh[3]);
                    mma_bf16(acc[mt][np*2+0], ah[mt], bl[0], bl[2]);
                    mma_bf16(acc[mt][np*2+1], ah[mt], bl[1], bl[3]);
                    mma_bf16(acc[mt][np*2+0], al[mt], bh[0], bh[2]);
                    mma_bf16(acc[mt][np*2+1], al[mt], bh[1], bh[3]);
                }
            }
        }
    }
    #pragma unroll
    for (int mt = 0; mt < 2; mt++) {
        const int row0 = m0 + wm * 32 + mt * 16 + (lane >> 2);
        #pragma unroll
        for (int nf = 0; nf < 8; nf++) {
            const int col = wn * 64 + nf * 8 + (lane & 3) * 2;
            *(float2*)(g_h + (size_t)row0 * DIM + col) =
                make_float2(acc[mt][nf][0], acc[mt][nf][1]);
            *(float2*)(g_h + (size_t)(row0 + 8) * DIM + col) =
                make_float2(acc[mt][nf][2], acc[mt][nf][3]);
        }
    }
}

// ---------------- K2: a_src / a_dst (warp per row, float4) ------------------
__global__ __launch_bounds__(256) void k2_coef(const float* __restrict__ Ws)
{
    const int lane = threadIdx.x & 31;
    const int row  = blockIdx.x * 8 + (threadIdx.x >> 5);
    const float* hr = g_h + (size_t)row * DIM + lane * 8;
    float4 h0 = *(const float4*)hr;
    float4 h1 = *(const float4*)(hr + 4);
    float4 s0 = *(const float4*)(Ws + lane * 8);
    float4 s1 = *(const float4*)(Ws + lane * 8 + 4);
    float4 d0 = *(const float4*)(Ws + DIM + lane * 8);
    float4 d1 = *(const float4*)(Ws + DIM + lane * 8 + 4);
    float ps = h0.x*s0.x + h0.y*s0.y + h0.z*s0.z + h0.w*s0.w
             + h1.x*s1.x + h1.y*s1.y + h1.z*s1.z + h1.w*s1.w;
    float pd = h0.x*d0.x + h0.y*d0.y + h0.z*d0.z + h0.w*d0.w
             + h1.x*d1.x + h1.y*d1.y + h1.z*d1.z + h1.w*d1.w;
    #pragma unroll
    for (int o = 16; o > 0; o >>= 1) {
        ps += __shfl_xor_sync(0xffffffffu, ps, o);
        pd += __shfl_xor_sync(0xffffffffu, pd, o);
    }
    if (lane == 0) { g_asrc[row] = ps; g_adst[row] = pd; }
}

// ---------------- K2b: transpose + bf16 split  h -> hT_hi/lo [b][d][j] ------
__global__ __launch_bounds__(256) void k2b_split()
{
    __shared__ float tile[32][33];
    const int b = blockIdx.z, j0 = blockIdx.x * 32, d0 = blockIdx.y * 32;
    const int c = threadIdx.x & 31, r0 = threadIdx.x >> 5;
    #pragma unroll
    for (int k = 0; k < 4; k++) {
        int r = r0 + k * 8;
        tile[r][c] = g_h[((size_t)(b * NSEQ + j0 + r)) * DIM + d0 + c];
    }
    __syncthreads();
    #pragma unroll
    for (int k = 0; k < 4; k++) {
        int r = r0 + k * 8;           // d offset within tile
        float v = tile[c][r];
        __nv_bfloat16 hb, lb;
        split_bf16(v, hb, lb);
        size_t o = ((size_t)(b * DIM + d0 + r)) * NSEQ + j0 + c;
        g_hT_hi[o] = hb;
        g_hT_lo[o] = lb;
    }
}

// ---------------- K3: write I_A + full softmax P (bf16 hi/lo) ---------------
// One block per (i,b); thread t handles 8 contiguous j. Vectorized int4/float4.
__global__ __launch_bounds__(256) void k3_ia_p(const int*   __restrict__ adj,
                                               const float* __restrict__ bsv,
                                               float*       __restrict__ outIA)
{
    const int i = blockIdx.x;
    const int b = blockIdx.y;
    const int t = threadIdx.x;
    const int lane = t & 31, warp = t >> 5;
    const int j0 = t * 8;
    const size_t rbase = ((size_t)b * NSEQ + i) * NSEQ;
    const float asrc = g_asrc[b * NSEQ + i];
    const float bs0  = bsv[0];

    int4 a0 = *(const int4*)(adj + rbase + j0);
    int4 a1 = *(const int4*)(adj + rbase + j0 + 4);
    const int av[8] = {a0.x, a0.y, a0.z, a0.w, a1.x, a1.y, a1.z, a1.w};
    float ad[8];
    *(float4*)(ad)     = *(const float4*)(g_adst + b * NSEQ + j0);
    *(float4*)(ad + 4) = *(const float4*)(g_adst + b * NSEQ + j0 + 4);

    float sc[8], iav[8];
    float mx = -3.0e38f;
    #pragma unroll
    for (int e = 0; e < 8; e++) {
        const int j = j0 + e;
        float x = asrc + ad[e] + bs0;
        float attn = (j < i) ? fsigmoid(x) : 0.0f;
        float ia = ((j == i) ? 1.0f : 0.0f) - attn;
        iav[e] = ia;
        float s = ((j <= i) && (av[e] == 1)) ? ia : NEGV;
        sc[e] = s;
        mx = fmaxf(mx, s);
    }
    *(float4*)(outIA + rbase + j0)     = *(float4*)(iav);
    *(float4*)(outIA + rbase + j0 + 4) = *(float4*)(iav + 4);

    __shared__ float redm[8], reds[8];
    #pragma unroll
    for (int o = 16; o > 0; o >>= 1) mx = fmaxf(mx, __shfl_xor_sync(0xffffffffu, mx, o));
    if (lane == 0) redm[warp] = mx;
    __syncthreads();
    float bm = redm[0];
    #pragma unroll
    for (int w = 1; w < 8; w++) bm = fmaxf(bm, redm[w]);

    float ex[8];
    float sum = 0.f;
    #pragma unroll
    for (int e = 0; e < 8; e++) { ex[e] = __expf(sc[e] - bm); sum += ex[e]; }
    #pragma unroll
    for (int o = 16; o > 0; o >>= 1) sum += __shfl_xor_sync(0xffffffffu, sum, o);
    if (lane == 0) reds[warp] = sum;
    __syncthreads();
    float tot = 0.f;
    #pragma unroll
    for (int w = 0; w < 8; w++) tot += reds[w];
    const float inv = __fdividef(1.0f, tot);

    union { __nv_bfloat16 h[8]; uint4 v; } Uh, Ul;
    #pragma unroll
    for (int e = 0; e < 8; e++) {
        float pv = ex[e] * inv;
        split_bf16(pv, Uh.h[e], Ul.h[e]);
    }
    *(uint4*)(g_P_hi + rbase + j0) = Uh.v;
    *(uint4*)(g_P_lo + rbase + j0) = Ul.v;
}

// ---------------- K4: feat_out = P @ h + b — pure GEMM now ------------------
// CTA: M=64 (i), N=256 (d), K=2048 (j, 32 chunks of 64). 8 warps = 2(m) x 4(n).
#define KCH 64
__global__ __launch_bounds__(256, 2) void k4_mma(const float* __restrict__ bias,
                                                 float*       __restrict__ outFO)
{
    extern __shared__ char sm[];
    char* sA_hi = sm;
    char* sA_lo = sm + 9216;
    char* sB_hi = sm + 18432;
    char* sB_lo = sm + 55296;

    const int t    = threadIdx.x;
    const int lane = t & 31;
    const int wid  = t >> 5;
    const int wm   = wid & 1;
    const int wn   = wid >> 1;
    const int b    = blockIdx.y;
    const int i0   = blockIdx.x * 64;

    const unsigned lrow = (lane & 15);
    const unsigned lcol = (lane >> 4) << 4;
    const unsigned aBase0 = smem_u32(sA_hi) + (wm * 32 + lrow) * PITCHB + lcol;
    const unsigned bBase0 = smem_u32(sB_hi) + (wn * 64 + lrow) * PITCHB + lcol;

    float acc[2][8][4] = {};

    for (int c = 0; c < NSEQ / KCH; c++) {
        const int j0 = c * KCH;
        __syncthreads();                 // previous chunk's mma done

        // ---- A tile: P 64 x 64 hi/lo (plain copies) ----
        #pragma unroll
        for (int q = 0; q < 2; q++) {
            const int idx = q * 256 + t;
            const int row = idx >> 3, seg = idx & 7;
            const size_t go = ((size_t)(b * NSEQ + i0 + row)) * NSEQ + j0 + seg * 8;
            const unsigned off = row * PITCHB + seg * 16;
            *(uint4*)(sA_hi + off) = *(const uint4*)(g_P_hi + go);
            *(uint4*)(sA_lo + off) = *(const uint4*)(g_P_lo + go);
        }
        // ---- B tile: h^T 256 x 64 hi/lo ----
        #pragma unroll
        for (int q = 0; q < 8; q++) {
            const int idx = q * 256 + t;
            const int d = idx >> 3, seg = idx & 7;
            const size_t go = ((size_t)(b * DIM + d)) * NSEQ + j0 + seg * 8;
            const unsigned off = d * PITCHB + seg * 16;
            *(uint4*)(sB_hi + off) = *(const uint4*)(g_hT_hi + go);
            *(uint4*)(sB_lo + off) = *(const uint4*)(g_hT_lo + go);
        }
        __syncthreads();

        // ---- mma mainloop over 4 k-steps ----
        #pragma unroll
        for (int ks = 0; ks < 4; ks++) {
            unsigned ah[2][4], al[2][4];
            #pragma unroll
            for (int mt = 0; mt < 2; mt++) {
                ldsm_x4(ah[mt], aBase0 + mt * 16 * PITCHB + ks * 32);
                ldsm_x4(al[mt], aBase0 + 9216u + mt * 16 * PITCHB + ks * 32);
            }
            #pragma unroll
            for (int np = 0; np < 4; np++) {
                unsigned bh[4], bl[4];
                ldsm_x4(bh, bBase0 + np * 16 * PITCHB + ks * 32);
                ldsm_x4(bl, bBase0 + 36864u + np * 16 * PITCHB + ks * 32);
                #pragma unroll
                for (int mt = 0; mt < 2; mt++) {
                    mma_bf16(acc[mt][np*2+0], ah[mt], bh[0], bh[2]);   // hi*hi
                    mma_bf16(acc[mt][np*2+1], ah[mt], bh[1], bh[3]);
                    mma_bf16(acc[mt][np*2+0], ah[mt], bl[0], bl[2]);   // hi*lo
                    mma_bf16(acc[mt][np*2+1], ah[mt], bl[1], bl[3]);
                    mma_bf16(acc[mt][np*2+0], al[mt], bh[0], bh[2]);   // lo*hi
                    mma_bf16(acc[mt][np*2+1], al[mt], bh[1], bh[3]);
                }
            }
        }
    }

    // ---- epilogue: accum + bias -> outFO ----
    #pragma unroll
    for (int mt = 0; mt < 2; mt++) {
        const int row0 = i0 + wm * 32 + mt * 16 + (lane >> 2);
        #pragma unroll
        for (int nf = 0; nf < 8; nf++) {
            const int col = wn * 64 + nf * 8 + (lane & 3) * 2;
            const float b0 = bias[col], b1 = bias[col + 1];
            float2 v0 = make_float2(acc[mt][nf][0] + b0, acc[mt][nf][1] + b1);
            float2 v1 = make_float2(acc[mt][nf][2] + b0, acc[mt][nf][3] + b1);
            *(float2*)(outFO + ((size_t)(b * NSEQ + row0)) * DIM + col) = v0;
            *(float2*)(outFO + ((size_t)(b * NSEQ + row0 + 8)) * DIM + col) = v1;
        }
    }
}

// ---------------- K5: gate = sigmoid(X@Hw^T+Hb), blend, via mma.sync --------
__global__ __launch_bounds__(256, 2) void k5_mma(const float* __restrict__ X,
                                                 const float* __restrict__ Hb,
                                                 float*       __restrict__ out)
{
    extern __shared__ char sm[];
    char* sA_hi = sm;
    char* sA_lo = sm + 9216;
    char* sB_hi = sm + 18432;
    char* sB_lo = sm + 55296;

    const int t    = threadIdx.x;
    const int lane = t & 31;
    const int wid  = t >> 5;
    const int wm   = wid & 1;
    const int wn   = wid >> 1;
    const int m0   = blockIdx.x * 64;

    const unsigned lrow = (lane & 15);
    const unsigned lcol = (lane >> 4) << 4;
    const unsigned aBase0 = smem_u32(sA_hi) + (wm * 32 + lrow) * PITCHB + lcol;
    const unsigned bBase0 = smem_u32(sB_hi) + (wn * 64 + lrow) * PITCHB + lcol;

    float acc[2][8][4] = {};

    for (int kc = 0; kc < 4; kc++) {
        const int j0 = kc * 64;
        __syncthreads();
        #pragma unroll
        for (int q = 0; q < 2; q++) {
            const int idx = q * 256 + t;
            const int row = idx >> 3, seg = idx & 7;
            const size_t go = (size_t)(m0 + row) * DIM + j0 + seg * 8;
            const unsigned off = row * PITCHB + seg * 16;
            *(uint4*)(sA_hi + off) = *(const uint4*)(g_X_hi + go);
            *(uint4*)(sA_lo + off) = *(const uint4*)(g_X_lo + go);
        }
        #pragma unroll
        for (int q = 0; q < 8; q++) {
            const int idx = q * 256 + t;
            const int d = idx >> 3, seg = idx & 7;
            const size_t go = (size_t)d * DIM + j0 + seg * 8;
            const unsigned off = d * PITCHB + seg * 16;
            *(uint4*)(sB_hi + off) = *(const uint4*)(g_Hw_hi + go);
            *(uint4*)(sB_lo + off) = *(const uint4*)(g_Hw_lo + go);
        }
        __syncthreads();
        #pragma unroll
        for (int ks = 0; ks < 4; ks++) {
            unsigned ah[2][4], al[2][4];
            #pragma unroll
            for (int mt = 0; mt < 2; mt++) {
                ldsm_x4(ah[mt], aBase0 + mt * 16 * PITCHB + ks * 32);
                ldsm_x4(al[mt], aBase0 + 9216u + mt * 16 * PITCHB + ks * 32);
            }
            #pragma unroll
            for (int np = 0; np < 4; np++) {
                unsigned bh[4], bl[4];
                ldsm_x4(bh, bBase0 + np * 16 * PITCHB + ks * 32);
                ldsm_x4(bl, bBase0 + 36864u + np * 16 * PITCHB + ks * 32);
                #pragma unroll
                for (int mt = 0; mt < 2; mt++) {
                    mma_bf16(acc[mt][np*2+0], ah[mt], bh[0], bh[2]);
                    mma_bf16(acc[mt][np*2+1], ah[mt], bh[1], bh[3]);
                    mma_bf16(acc[mt][np*2+0], ah[mt], bl[0], bl[2]);
                    mma_bf16(acc[mt][np*2+1], ah[mt], bl[1], bl[3]);
                    mma_bf16(acc[mt][np*2+0], al[mt], bh[0], bh[2]);
                    mma_bf16(acc[mt][np*2+1], al[mt], bh[1], bh[3]);
                }
            }
        }
    }

    // epilogue: gate + elu + blend (out holds feat_out pre-activation)
    #pragma unroll
    for (int mt = 0; mt < 2; mt++) {
        const int row0 = m0 + wm * 32 + mt * 16 + (lane >> 2);
        #pragma unroll
        for (int nf = 0; nf < 8; nf++) {
            const int col = wn * 64 + nf * 8 + (lane & 3) * 2;
            const float hb0 = Hb[col], hb1 = Hb[col + 1];
            #pragma unroll
            for (int rr = 0; rr < 2; rr++) {
                const size_t o = (size_t)(row0 + rr * 8) * DIM + col;
                float2 fo = *(const float2*)(out + o);
                float2 xv = *(const float2*)(X + o);
                float g0 = fsigmoid(acc[mt][nf][rr*2+0] + hb0);
                float g1 = fsigmoid(acc[mt][nf][rr*2+1] + hb1);
                float e0 = (fo.x > 0.0f) ? fo.x : expm1f(fo.x);
                float e1 = (fo.y > 0.0f) ? fo.y : expm1f(fo.y);
                float2 r;
                r.x = g0 * e0 + (1.0f - g0) * xv.x;
                r.y = g1 * e1 + (1.0f - g1) * xv.y;
                *(float2*)(out + o) = r;
            }
        }
    }
}

// ---------------- launch ----------------------------------------------------
extern "C" void kernel_launch(void* const* d_in, const int* in_sizes, int n_in,
                              void* d_out, int out_size)
{
    const float* feat = (const float*)d_in[0];
    const int*   adj  = (const int*)  d_in[1];
    const float* W    = (const float*)d_in[2];
    const float* bvec = (const float*)d_in[3];
    const float* Ws   = (const float*)d_in[4];
    const float* bs   = (const float*)d_in[5];
    const float* Hw   = (const float*)d_in[6];
    const float* Hb   = (const float*)d_in[7];

    float* out   = (float*)d_out;                      // (B,N,256)
    float* outIA = out + (size_t)NROWS * DIM;          // (B,1,N,N)

    cudaFuncSetAttribute(k1_mma, cudaFuncAttributeMaxDynamicSharedMemorySize, 92160);
    cudaFuncSetAttribute(k4_mma, cudaFuncAttributeMaxDynamicSharedMemorySize, 92160);
    cudaFuncSetAttribute(k5_mma, cudaFuncAttributeMaxDynamicSharedMemorySize, 92160);

    k0a_splitX<<<NROWS * DIM / 1024, 256>>>(feat);
    k0b_splitW<<<DIM, DIM>>>(W, Hw);
    k1_mma   <<<NROWS / 64, 256, 92160>>>();
    k2_coef  <<<NROWS / 8, 256>>>(Ws);
    k2b_split<<<dim3(NSEQ / 32, DIM / 32, BATCH), 256>>>();
    k3_ia_p  <<<dim3(NSEQ, BATCH), 256>>>(adj, bs, outIA);
    k4_mma   <<<dim3(NSEQ / 64, BATCH), 256, 92160>>>(bvec, out);
    k5_mma   <<<NROWS / 64, 256, 92160>>>(feat, Hb, out);
}

// round 9
// speedup vs baseline: 1.5657x; 1.0086x over previous
#include <cuda_runtime.h>
#include <cuda_bf16.h>

#define BATCH 8
#define NSEQ  2048
#define DIM   256
#define NROWS (BATCH * NSEQ)          // 16384
#define NEGV  (-999999.0f)

// ---------------- scratch (device globals; no allocation allowed) ----------
__device__ float g_h[(size_t)NROWS * DIM];              // h = X @ W   (16.8 MB)
__device__ __nv_bfloat16 g_hT_hi[(size_t)NROWS * DIM];  // h^T split hi [b][d][j]
__device__ __nv_bfloat16 g_hT_lo[(size_t)NROWS * DIM];  // h^T split lo [b][d][j]
__device__ __nv_bfloat16 g_X_hi[(size_t)NROWS * DIM];   // feat split  [m][k]
__device__ __nv_bfloat16 g_X_lo[(size_t)NROWS * DIM];
__device__ __nv_bfloat16 g_WT_hi[DIM * DIM];            // W^T split   [n][k]
__device__ __nv_bfloat16 g_WT_lo[DIM * DIM];
__device__ __nv_bfloat16 g_Hw_hi[DIM * DIM];            // Hw split    [n][k]
__device__ __nv_bfloat16 g_Hw_lo[DIM * DIM];
__device__ __nv_bfloat16 g_P_hi[(size_t)NROWS * NSEQ];  // softmax P split (67MB)
__device__ __nv_bfloat16 g_P_lo[(size_t)NROWS * NSEQ];
__device__ float g_asrc[NROWS];
__device__ float g_adst[NROWS];

__device__ __forceinline__ float fsigmoid(float x) {
    return __fdividef(1.0f, 1.0f + __expf(-x));
}

__device__ __forceinline__ unsigned smem_u32(const void* p) {
    unsigned a;
    asm("{ .reg .u64 t; cvta.to.shared.u64 t, %1; cvt.u32.u64 %0, t; }"
        : "=r"(a) : "l"(p));
    return a;
}

__device__ __forceinline__ void ldsm_x4(unsigned r[4], unsigned addr) {
    asm volatile("ldmatrix.sync.aligned.m8n8.x4.shared.b16 {%0,%1,%2,%3}, [%4];"
                 : "=r"(r[0]), "=r"(r[1]), "=r"(r[2]), "=r"(r[3]) : "r"(addr));
}

__device__ __forceinline__ void mma_bf16(float c[4], const unsigned a[4],
                                         unsigned b0, unsigned b1) {
    asm volatile("mma.sync.aligned.m16n8k16.row.col.f32.bf16.bf16.f32 "
                 "{%0,%1,%2,%3}, {%4,%5,%6,%7}, {%8,%9}, {%0,%1,%2,%3};"
                 : "+f"(c[0]), "+f"(c[1]), "+f"(c[2]), "+f"(c[3])
                 : "r"(a[0]), "r"(a[1]), "r"(a[2]), "r"(a[3]), "r"(b0), "r"(b1));
}

__device__ __forceinline__ void split_bf16(float v, __nv_bfloat16& hi, __nv_bfloat16& lo) {
    hi = __float2bfloat16_rn(v);
    lo = __float2bfloat16_rn(v - __bfloat162float(hi));
}

__device__ __forceinline__ void cp_async16(unsigned saddr, const void* gptr) {
    asm volatile("cp.async.cg.shared.global [%0], [%1], 16;"
                 :: "r"(saddr), "l"(gptr) : "memory");
}
#define CP_COMMIT() asm volatile("cp.async.commit_group;" ::: "memory")
#define CP_WAIT(N)  asm volatile("cp.async.wait_group %0;" :: "n"(N) : "memory")

#define PITCHB 144

// ---------------- K0a: split X (feat) into bf16 hi/lo -----------------------
__global__ __launch_bounds__(256) void k0a_splitX(const float* __restrict__ X)
{
    const size_t base = (size_t)blockIdx.x * 1024 + threadIdx.x * 4;
    float4 v = *(const float4*)(X + base);
    union { __nv_bfloat16 h[4]; uint2 u; } Uh, Ul;
    split_bf16(v.x, Uh.h[0], Ul.h[0]);
    split_bf16(v.y, Uh.h[1], Ul.h[1]);
    split_bf16(v.z, Uh.h[2], Ul.h[2]);
    split_bf16(v.w, Uh.h[3], Ul.h[3]);
    *(uint2*)(g_X_hi + base) = Uh.u;
    *(uint2*)(g_X_lo + base) = Ul.u;
}

// ---------------- K0b: W^T split + Hw split ---------------------------------
__global__ __launch_bounds__(256) void k0b_splitW(const float* __restrict__ W,
                                                  const float* __restrict__ Hw)
{
    const int n = blockIdx.x;            // 0..255
    const int k = threadIdx.x;           // 0..255
    split_bf16(W[k * DIM + n], g_WT_hi[n * DIM + k], g_WT_lo[n * DIM + k]);
    split_bf16(Hw[n * DIM + k], g_Hw_hi[n * DIM + k], g_Hw_lo[n * DIM + k]);
}

// ---------------- K1: h = X @ W via mma.sync bf16 split ---------------------
__global__ __launch_bounds__(256, 2) void k1_mma()
{
    extern __shared__ char sm[];
    char* sA_hi = sm;
    char* sA_lo = sm + 9216;
    char* sB_hi = sm + 18432;
    char* sB_lo = sm + 55296;

    const int t    = threadIdx.x;
    const int lane = t & 31;
    const int wid  = t >> 5;
    const int wm   = wid & 1;
    const int wn   = wid >> 1;
    const int m0   = blockIdx.x * 64;

    const unsigned lrow = (lane & 15);
    const unsigned lcol = (lane >> 4) << 4;
    const unsigned aBase0 = smem_u32(sA_hi) + (wm * 32 + lrow) * PITCHB + lcol;
    const unsigned bBase0 = smem_u32(sB_hi) + (wn * 64 + lrow) * PITCHB + lcol;

    float acc[2][8][4] = {};

    for (int kc = 0; kc < 4; kc++) {
        const int j0 = kc * 64;
        __syncthreads();
        #pragma unroll
        for (int q = 0; q < 2; q++) {
            const int idx = q * 256 + t;
            const int row = idx >> 3, seg = idx & 7;
            const size_t go = (size_t)(m0 + row) * DIM + j0 + seg * 8;
            const unsigned off = row * PITCHB + seg * 16;
            *(uint4*)(sA_hi + off) = *(const uint4*)(g_X_hi + go);
            *(uint4*)(sA_lo + off) = *(const uint4*)(g_X_lo + go);
        }
        #pragma unroll
        for (int q = 0; q < 8; q++) {
            const int idx = q * 256 + t;
            const int d = idx >> 3, seg = idx & 7;
            const size_t go = (size_t)d * DIM + j0 + seg * 8;
            const unsigned off = d * PITCHB + seg * 16;
            *(uint4*)(sB_hi + off) = *(const uint4*)(g_WT_hi + go);
            *(uint4*)(sB_lo + off) = *(const uint4*)(g_WT_lo + go);
        }
        __syncthreads();
        #pragma unroll
        for (int ks = 0; ks < 4; ks++) {
            unsigned ah[2][4], al[2][4];
            #pragma unroll
            for (int mt = 0; mt < 2; mt++) {
                ldsm_x4(ah[mt], aBase0 + mt * 16 * PITCHB + ks * 32);
                ldsm_x4(al[mt], aBase0 + 9216u + mt * 16 * PITCHB + ks * 32);
            }
            #pragma unroll
            for (int np = 0; np < 4; np++) {
                unsigned bh[4], bl[4];
                ldsm_x4(bh, bBase0 + np * 16 * PITCHB + ks * 32);
                ldsm_x4(bl, bBase0 + 36864u + np * 16 * PITCHB + ks * 32);
                #pragma unroll
                for (int mt = 0; mt < 2; mt++) {
                    mma_bf16(acc[mt][np*2+0], ah[mt], bh[0], bh[2]);
                    mma_bf16(acc[mt][np*2+1], ah[mt], bh[1], bh[3]);
                    mma_bf16(acc[mt][np*2+0], ah[mt], bl[0], bl[2]);
                    mma_bf16(acc[mt][np*2+1], ah[mt], bl[1], bl[3]);
                    mma_bf16(acc[mt][np*2+0], al[mt], bh[0], bh[2]);
                    mma_bf16(acc[mt][np*2+1], al[mt], bh[1], bh[3]);
                }
            }
        }
    }
    #pragma unroll
    for (int mt = 0; mt < 2; mt++) {
        const int row0 = m0 + wm * 32 + mt * 16 + (lane >> 2);
        #pragma unroll
        for (int nf = 0; nf < 8; nf++) {
            const int col = wn * 64 + nf * 8 + (lane & 3) * 2;
            *(float2*)(g_h + (size_t)row0 * DIM + col) =
                make_float2(acc[mt][nf][0], acc[mt][nf][1]);
            *(float2*)(g_h + (size_t)(row0 + 8) * DIM + col) =
                make_float2(acc[mt][nf][2], acc[mt][nf][3]);
        }
    }
}

// ---------------- K2: a_src / a_dst (warp per row, float4) ------------------
__global__ __launch_bounds__(256) void k2_coef(const float* __restrict__ Ws)
{
    const int lane = threadIdx.x & 31;
    const int row  = blockIdx.x * 8 + (threadIdx.x >> 5);
    const float* hr = g_h + (size_t)row * DIM + lane * 8;
    float4 h0 = *(const float4*)hr;
    float4 h1 = *(const float4*)(hr + 4);
    float4 s0 = *(const float4*)(Ws + lane * 8);
    float4 s1 = *(const float4*)(Ws + lane * 8 + 4);
    float4 d0 = *(const float4*)(Ws + DIM + lane * 8);
    float4 d1 = *(const float4*)(Ws + DIM + lane * 8 + 4);
    float ps = h0.x*s0.x + h0.y*s0.y + h0.z*s0.z + h0.w*s0.w
             + h1.x*s1.x + h1.y*s1.y + h1.z*s1.z + h1.w*s1.w;
    float pd = h0.x*d0.x + h0.y*d0.y + h0.z*d0.z + h0.w*d0.w
             + h1.x*d1.x + h1.y*d1.y + h1.z*d1.z + h1.w*d1.w;
    #pragma unroll
    for (int o = 16; o > 0; o >>= 1) {
        ps += __shfl_xor_sync(0xffffffffu, ps, o);
        pd += __shfl_xor_sync(0xffffffffu, pd, o);
    }
    if (lane == 0) { g_asrc[row] = ps; g_adst[row] = pd; }
}

// ---------------- K2b: transpose + bf16 split  h -> hT_hi/lo [b][d][j] ------
__global__ __launch_bounds__(256) void k2b_split()
{
    __shared__ float tile[32][33];
    const int b = blockIdx.z, j0 = blockIdx.x * 32, d0 = blockIdx.y * 32;
    const int c = threadIdx.x & 31, r0 = threadIdx.x >> 5;
    #pragma unroll
    for (int k = 0; k < 4; k++) {
        int r = r0 + k * 8;
        tile[r][c] = g_h[((size_t)(b * NSEQ + j0 + r)) * DIM + d0 + c];
    }
    __syncthreads();
    #pragma unroll
    for (int k = 0; k < 4; k++) {
        int r = r0 + k * 8;           // d offset within tile
        float v = tile[c][r];
        __nv_bfloat16 hb, lb;
        split_bf16(v, hb, lb);
        size_t o = ((size_t)(b * DIM + d0 + r)) * NSEQ + j0 + c;
        g_hT_hi[o] = hb;
        g_hT_lo[o] = lb;
    }
}

// ---------------- K3: write I_A + full softmax P (bf16 hi/lo) ---------------
__global__ __launch_bounds__(256) void k3_ia_p(const int*   __restrict__ adj,
                                               const float* __restrict__ bsv,
                                               float*       __restrict__ outIA)
{
    const int i = blockIdx.x;
    const int b = blockIdx.y;
    const int t = threadIdx.x;
    const int lane = t & 31, warp = t >> 5;
    const int j0 = t * 8;
    const size_t rbase = ((size_t)b * NSEQ + i) * NSEQ;
    const float asrc = g_asrc[b * NSEQ + i];
    const float bs0  = bsv[0];

    int4 a0 = *(const int4*)(adj + rbase + j0);
    int4 a1 = *(const int4*)(adj + rbase + j0 + 4);
    const int av[8] = {a0.x, a0.y, a0.z, a0.w, a1.x, a1.y, a1.z, a1.w};
    float ad[8];
    *(float4*)(ad)     = *(const float4*)(g_adst + b * NSEQ + j0);
    *(float4*)(ad + 4) = *(const float4*)(g_adst + b * NSEQ + j0 + 4);

    float sc[8], iav[8];
    float mx = -3.0e38f;
    #pragma unroll
    for (int e = 0; e < 8; e++) {
        const int j = j0 + e;
        float x = asrc + ad[e] + bs0;
        float attn = (j < i) ? fsigmoid(x) : 0.0f;
        float ia = ((j == i) ? 1.0f : 0.0f) - attn;
        iav[e] = ia;
        float s = ((j <= i) && (av[e] == 1)) ? ia : NEGV;
        sc[e] = s;
        mx = fmaxf(mx, s);
    }
    *(float4*)(outIA + rbase + j0)     = *(float4*)(iav);
    *(float4*)(outIA + rbase + j0 + 4) = *(float4*)(iav + 4);

    __shared__ float redm[8], reds[8];
    #pragma unroll
    for (int o = 16; o > 0; o >>= 1) mx = fmaxf(mx, __shfl_xor_sync(0xffffffffu, mx, o));
    if (lane == 0) redm[warp] = mx;
    __syncthreads();
    float bm = redm[0];
    #pragma unroll
    for (int w = 1; w < 8; w++) bm = fmaxf(bm, redm[w]);

    float ex[8];
    float sum = 0.f;
    #pragma unroll
    for (int e = 0; e < 8; e++) { ex[e] = __expf(sc[e] - bm); sum += ex[e]; }
    #pragma unroll
    for (int o = 16; o > 0; o >>= 1) sum += __shfl_xor_sync(0xffffffffu, sum, o);
    if (lane == 0) reds[warp] = sum;
    __syncthreads();
    float tot = 0.f;
    #pragma unroll
    for (int w = 0; w < 8; w++) tot += reds[w];
    const float inv = __fdividef(1.0f, tot);

    union { __nv_bfloat16 h[8]; uint4 v; } Uh, Ul;
    #pragma unroll
    for (int e = 0; e < 8; e++) {
        float pv = ex[e] * inv;
        split_bf16(pv, Uh.h[e], Ul.h[e]);
    }
    *(uint4*)(g_P_hi + rbase + j0) = Uh.v;
    *(uint4*)(g_P_lo + rbase + j0) = Ul.v;
}

// ---------------- K4: feat_out = P @ h + b — M=128, cp.async pipeline -------
// CTA: M=128 (i), N=256 (d), K=2048 (32 chunks of 64). 512 threads = 16 warps
// (4m x 4n, warp tile m32 x n64). Double-buffered SMEM via cp.async.
// Buffer layout (110592 B each): A_hi @0 (18432), A_lo @18432,
//                                B_hi @36864 (36864), B_lo @73728.
#define KCH    64
#define BUF_SZ 110592u
__device__ __forceinline__ void k4_prefetch(int b, int i0, int j0, unsigned sb)
{
    const int t = threadIdx.x;
    #pragma unroll
    for (int q = 0; q < 2; q++) {
        const int idx = q * 512 + t;
        const int row = idx >> 3, seg = idx & 7;
        const size_t go = ((size_t)(b * NSEQ + i0 + row)) * NSEQ + j0 + seg * 8;
        const unsigned off = row * PITCHB + seg * 16;
        cp_async16(sb + off,          g_P_hi + go);
        cp_async16(sb + 18432u + off, g_P_lo + go);
    }
    #pragma unroll
    for (int q = 0; q < 4; q++) {
        const int idx = q * 512 + t;
        const int d = idx >> 3, seg = idx & 7;
        const size_t go = ((size_t)(b * DIM + d)) * NSEQ + j0 + seg * 8;
        const unsigned off = d * PITCHB + seg * 16;
        cp_async16(sb + 36864u + off, g_hT_hi + go);
        cp_async16(sb + 73728u + off, g_hT_lo + go);
    }
}

__global__ __launch_bounds__(512, 1) void k4_mma(const float* __restrict__ bias,
                                                 float*       __restrict__ outFO)
{
    extern __shared__ char sm[];
    const int t    = threadIdx.x;
    const int lane = t & 31;
    const int wid  = t >> 5;
    const int wm   = wid & 3;           // 4 m-warps -> 32 rows each
    const int wn   = wid >> 2;          // 4 n-warps -> 64 cols each
    const int b    = blockIdx.y;
    const int i0   = blockIdx.x * 128;

    const unsigned smb  = smem_u32(sm);
    const unsigned lrow = (lane & 15);
    const unsigned lcol = (lane >> 4) << 4;
    const unsigned aBase0 = smb + (wm * 32 + lrow) * PITCHB + lcol;            // A_hi
    const unsigned bBase0 = smb + 36864u + (wn * 64 + lrow) * PITCHB + lcol;   // B_hi

    float acc[2][8][4] = {};

    k4_prefetch(b, i0, 0, smb);
    CP_COMMIT();

    for (int c = 0; c < NSEQ / KCH; c++) {
        const unsigned bufOff = (c & 1) * BUF_SZ;
        if (c + 1 < NSEQ / KCH) {
            k4_prefetch(b, i0, (c + 1) * KCH, smb + ((c + 1) & 1) * BUF_SZ);
            CP_COMMIT();
            CP_WAIT(1);                    // chunk c resident
        } else {
            CP_WAIT(0);
        }
        __syncthreads();

        #pragma unroll
        for (int ks = 0; ks < 4; ks++) {
            unsigned ah[2][4], al[2][4];
            #pragma unroll
            for (int mt = 0; mt < 2; mt++) {
                ldsm_x4(ah[mt], aBase0 + bufOff + mt * 16 * PITCHB + ks * 32);
                ldsm_x4(al[mt], aBase0 + bufOff + 18432u + mt * 16 * PITCHB + ks * 32);
            }
            #pragma unroll
            for (int np = 0; np < 4; np++) {
                unsigned bh[4], bl[4];
                ldsm_x4(bh, bBase0 + bufOff + np * 16 * PITCHB + ks * 32);
                ldsm_x4(bl, bBase0 + bufOff + 36864u + np * 16 * PITCHB + ks * 32);
                #pragma unroll
                for (int mt = 0; mt < 2; mt++) {
                    mma_bf16(acc[mt][np*2+0], ah[mt], bh[0], bh[2]);   // hi*hi
                    mma_bf16(acc[mt][np*2+1], ah[mt], bh[1], bh[3]);
                    mma_bf16(acc[mt][np*2+0], ah[mt], bl[0], bl[2]);   // hi*lo
                    mma_bf16(acc[mt][np*2+1], ah[mt], bl[1], bl[3]);
                    mma_bf16(acc[mt][np*2+0], al[mt], bh[0], bh[2]);   // lo*hi
                    mma_bf16(acc[mt][np*2+1], al[mt], bh[1], bh[3]);
                }
            }
        }
        __syncthreads();                  // mma(c) done before buf overwrite
    }

    // ---- epilogue: accum + bias -> outFO ----
    #pragma unroll
    for (int mt = 0; mt < 2; mt++) {
        const int row0 = i0 + wm * 32 + mt * 16 + (lane >> 2);
        #pragma unroll
        for (int nf = 0; nf < 8; nf++) {
            const int col = wn * 64 + nf * 8 + (lane & 3) * 2;
            const float b0 = bias[col], b1 = bias[col + 1];
            float2 v0 = make_float2(acc[mt][nf][0] + b0, acc[mt][nf][1] + b1);
            float2 v1 = make_float2(acc[mt][nf][2] + b0, acc[mt][nf][3] + b1);
            *(float2*)(outFO + ((size_t)(b * NSEQ + row0)) * DIM + col) = v0;
            *(float2*)(outFO + ((size_t)(b * NSEQ + row0 + 8)) * DIM + col) = v1;
        }
    }
}

// ---------------- K5: gate = sigmoid(X@Hw^T+Hb), blend, via mma.sync --------
__global__ __launch_bounds__(256, 2) void k5_mma(const float* __restrict__ X,
                                                 const float* __restrict__ Hb,
                                                 float*       __restrict__ out)
{
    extern __shared__ char sm[];
    char* sA_hi = sm;
    char* sA_lo = sm + 9216;
    char* sB_hi = sm + 18432;
    char* sB_lo = sm + 55296;

    const int t    = threadIdx.x;
    const int lane = t & 31;
    const int wid  = t >> 5;
    const int wm   = wid & 1;
    const int wn   = wid >> 1;
    const int m0   = blockIdx.x * 64;

    const unsigned lrow = (lane & 15);
    const unsigned lcol = (lane >> 4) << 4;
    const unsigned aBase0 = smem_u32(sA_hi) + (wm * 32 + lrow) * PITCHB + lcol;
    const unsigned bBase0 = smem_u32(sB_hi) + (wn * 64 + lrow) * PITCHB + lcol;

    float acc[2][8][4] = {};

    for (int kc = 0; kc < 4; kc++) {
        const int j0 = kc * 64;
        __syncthreads();
        #pragma unroll
        for (int q = 0; q < 2; q++) {
            const int idx = q * 256 + t;
            const int row = idx >> 3, seg = idx & 7;
            const size_t go = (size_t)(m0 + row) * DIM + j0 + seg * 8;
            const unsigned off = row * PITCHB + seg * 16;
            *(uint4*)(sA_hi + off) = *(const uint4*)(g_X_hi + go);
            *(uint4*)(sA_lo + off) = *(const uint4*)(g_X_lo + go);
        }
        #pragma unroll
        for (int q = 0; q < 8; q++) {
            const int idx = q * 256 + t;
            const int d = idx >> 3, seg = idx & 7;
            const size_t go = (size_t)d * DIM + j0 + seg * 8;
            const unsigned off = d * PITCHB + seg * 16;
            *(uint4*)(sB_hi + off) = *(const uint4*)(g_Hw_hi + go);
            *(uint4*)(sB_lo + off) = *(const uint4*)(g_Hw_lo + go);
        }
        __syncthreads();
        #pragma unroll
        for (int ks = 0; ks < 4; ks++) {
            unsigned ah[2][4], al[2][4];
            #pragma unroll
            for (int mt = 0; mt < 2; mt++) {
                ldsm_x4(ah[mt], aBase0 + mt * 16 * PITCHB + ks * 32);
                ldsm_x4(al[mt], aBase0 + 9216u + mt * 16 * PITCHB + ks * 32);
            }
            #pragma unroll
            for (int np = 0; np < 4; np++) {
                unsigned bh[4], bl[4];
                ldsm_x4(bh, bBase0 + np * 16 * PITCHB + ks * 32);
                ldsm_x4(bl, bBase0 + 36864u + np * 16 * PITCHB + ks * 32);
                #pragma unroll
                for (int mt = 0; mt < 2; mt++) {
                    mma_bf16(acc[mt][np*2+0], ah[mt], bh[0], bh[2]);
                    mma_bf16(acc[mt][np*2+1], ah[mt], bh[1], bh[3]);
                    mma_bf16(acc[mt][np*2+0], ah[mt], bl[0], bl[2]);
                    mma_bf16(acc[mt][np*2+1], ah[mt], bl[1], bl[3]);
                    mma_bf16(acc[mt][np*2+0], al[mt], bh[0], bh[2]);
                    mma_bf16(acc[mt][np*2+1], al[mt], bh[1], bh[3]);
                }
            }
        }
    }

    // epilogue: gate + elu + blend (out holds feat_out pre-activation)
    #pragma unroll
    for (int mt = 0; mt < 2; mt++) {
        const int row0 = m0 + wm * 32 + mt * 16 + (lane >> 2);
        #pragma unroll
        for (int nf = 0; nf < 8; nf++) {
            const int col = wn * 64 + nf * 8 + (lane & 3) * 2;
            const float hb0 = Hb[col], hb1 = Hb[col + 1];
            #pragma unroll
            for (int rr = 0; rr < 2; rr++) {
                const size_t o = (size_t)(row0 + rr * 8) * DIM + col;
                float2 fo = *(const float2*)(out + o);
                float2 xv = *(const float2*)(X + o);
                float g0 = fsigmoid(acc[mt][nf][rr*2+0] + hb0);
                float g1 = fsigmoid(acc[mt][nf][rr*2+1] + hb1);
                float e0 = (fo.x > 0.0f) ? fo.x : expm1f(fo.x);
                float e1 = (fo.y > 0.0f) ? fo.y : expm1f(fo.y);
                float2 r;
                r.x = g0 * e0 + (1.0f - g0) * xv.x;
                r.y = g1 * e1 + (1.0f - g1) * xv.y;
                *(float2*)(out + o) = r;
            }
        }
    }
}

// ---------------- launch ----------------------------------------------------
extern "C" void kernel_launch(void* const* d_in, const int* in_sizes, int n_in,
                              void* d_out, int out_size)
{
    const float* feat = (const float*)d_in[0];
    const int*   adj  = (const int*)  d_in[1];
    const float* W    = (const float*)d_in[2];
    const float* bvec = (const float*)d_in[3];
    const float* Ws   = (const float*)d_in[4];
    const float* bs   = (const float*)d_in[5];
    const float* Hw   = (const float*)d_in[6];
    const float* Hb   = (const float*)d_in[7];

    float* out   = (float*)d_out;                      // (B,N,256)
    float* outIA = out + (size_t)NROWS * DIM;          // (B,1,N,N)

    cudaFuncSetAttribute(k1_mma, cudaFuncAttributeMaxDynamicSharedMemorySize, 92160);
    cudaFuncSetAttribute(k4_mma, cudaFuncAttributeMaxDynamicSharedMemorySize, 2 * BUF_SZ);
    cudaFuncSetAttribute(k5_mma, cudaFuncAttributeMaxDynamicSharedMemorySize, 92160);

    k0a_splitX<<<NROWS * DIM / 1024, 256>>>(feat);
    k0b_splitW<<<DIM, DIM>>>(W, Hw);
    k1_mma   <<<NROWS / 64, 256, 92160>>>();
    k2_coef  <<<NROWS / 8, 256>>>(Ws);
    k2b_split<<<dim3(NSEQ / 32, DIM / 32, BATCH), 256>>>();
    k3_ia_p  <<<dim3(NSEQ, BATCH), 256>>>(adj, bs, outIA);
    k4_mma   <<<dim3(NSEQ / 128, BATCH), 512, 2 * BUF_SZ>>>(bvec, out);
    k5_mma   <<<NROWS / 64, 256, 92160>>>(feat, Hb, out);
}

// round 10
// speedup vs baseline: 1.9334x; 1.2348x over previous
#include <cuda_runtime.h>
#include <cuda_bf16.h>
#include <cuda_fp16.h>

#define BATCH 8
#define NSEQ  2048
#define DIM   256
#define NROWS (BATCH * NSEQ)          // 16384
#define NEGV  (-999999.0f)

// ---------------- scratch (device globals; no allocation allowed) ----------
__device__ float g_h[(size_t)NROWS * DIM];              // h = X @ W   (16.8 MB)
__device__ __half g_hT_hi[(size_t)NROWS * DIM];         // h^T fp16 split hi [b][d][j]
__device__ __half g_hT_lo[(size_t)NROWS * DIM];         // h^T fp16 split lo [b][d][j]
__device__ __nv_bfloat16 g_X_hi[(size_t)NROWS * DIM];   // feat split  [m][k]
__device__ __nv_bfloat16 g_X_lo[(size_t)NROWS * DIM];
__device__ __nv_bfloat16 g_WT_hi[DIM * DIM];            // W^T split   [n][k]
__device__ __nv_bfloat16 g_WT_lo[DIM * DIM];
__device__ __nv_bfloat16 g_Hw_hi[DIM * DIM];            // Hw split    [n][k]
__device__ __nv_bfloat16 g_Hw_lo[DIM * DIM];
__device__ __half g_P[(size_t)NROWS * NSEQ];            // softmax P fp16 (67MB)
__device__ float g_asrc[NROWS];
__device__ float g_adst[NROWS];

__device__ __forceinline__ float fsigmoid(float x) {
    return __fdividef(1.0f, 1.0f + __expf(-x));
}

__device__ __forceinline__ unsigned smem_u32(const void* p) {
    unsigned a;
    asm("{ .reg .u64 t; cvta.to.shared.u64 t, %1; cvt.u32.u64 %0, t; }"
        : "=r"(a) : "l"(p));
    return a;
}

__device__ __forceinline__ void ldsm_x4(unsigned r[4], unsigned addr) {
    asm volatile("ldmatrix.sync.aligned.m8n8.x4.shared.b16 {%0,%1,%2,%3}, [%4];"
                 : "=r"(r[0]), "=r"(r[1]), "=r"(r[2]), "=r"(r[3]) : "r"(addr));
}

__device__ __forceinline__ void mma_bf16(float c[4], const unsigned a[4],
                                         unsigned b0, unsigned b1) {
    asm volatile("mma.sync.aligned.m16n8k16.row.col.f32.bf16.bf16.f32 "
                 "{%0,%1,%2,%3}, {%4,%5,%6,%7}, {%8,%9}, {%0,%1,%2,%3};"
                 : "+f"(c[0]), "+f"(c[1]), "+f"(c[2]), "+f"(c[3])
                 : "r"(a[0]), "r"(a[1]), "r"(a[2]), "r"(a[3]), "r"(b0), "r"(b1));
}

__device__ __forceinline__ void mma_f16(float c[4], const unsigned a[4],
                                        unsigned b0, unsigned b1) {
    asm volatile("mma.sync.aligned.m16n8k16.row.col.f32.f16.f16.f32 "
                 "{%0,%1,%2,%3}, {%4,%5,%6,%7}, {%8,%9}, {%0,%1,%2,%3};"
                 : "+f"(c[0]), "+f"(c[1]), "+f"(c[2]), "+f"(c[3])
                 : "r"(a[0]), "r"(a[1]), "r"(a[2]), "r"(a[3]), "r"(b0), "r"(b1));
}

__device__ __forceinline__ void split_bf16(float v, __nv_bfloat16& hi, __nv_bfloat16& lo) {
    hi = __float2bfloat16_rn(v);
    lo = __float2bfloat16_rn(v - __bfloat162float(hi));
}

__device__ __forceinline__ void split_f16(float v, __half& hi, __half& lo) {
    hi = __float2half_rn(v);
    lo = __float2half_rn(v - __half2float(hi));
}

__device__ __forceinline__ void cp_async16(unsigned saddr, const void* gptr) {
    asm volatile("cp.async.cg.shared.global [%0], [%1], 16;"
                 :: "r"(saddr), "l"(gptr) : "memory");
}
#define CP_COMMIT() asm volatile("cp.async.commit_group;" ::: "memory")
#define CP_WAIT(N)  asm volatile("cp.async.wait_group %0;" :: "n"(N) : "memory")

#define PITCHB 144

// ---------------- K0a: split X (feat) into bf16 hi/lo -----------------------
__global__ __launch_bounds__(256) void k0a_splitX(const float* __restrict__ X)
{
    const size_t base = (size_t)blockIdx.x * 1024 + threadIdx.x * 4;
    float4 v = *(const float4*)(X + base);
    union { __nv_bfloat16 h[4]; uint2 u; } Uh, Ul;
    split_bf16(v.x, Uh.h[0], Ul.h[0]);
    split_bf16(v.y, Uh.h[1], Ul.h[1]);
    split_bf16(v.z, Uh.h[2], Ul.h[2]);
    split_bf16(v.w, Uh.h[3], Ul.h[3]);
    *(uint2*)(g_X_hi + base) = Uh.u;
    *(uint2*)(g_X_lo + base) = Ul.u;
}

// ---------------- K0b: W^T split + Hw split ---------------------------------
__global__ __launch_bounds__(256) void k0b_splitW(const float* __restrict__ W,
                                                  const float* __restrict__ Hw)
{
    const int n = blockIdx.x;            // 0..255
    const int k = threadIdx.x;           // 0..255
    split_bf16(W[k * DIM + n], g_WT_hi[n * DIM + k], g_WT_lo[n * DIM + k]);
    split_bf16(Hw[n * DIM + k], g_Hw_hi[n * DIM + k], g_Hw_lo[n * DIM + k]);
}

// ---------------- K1: h = X @ W via mma.sync bf16 split ---------------------
__global__ __launch_bounds__(256, 2) void k1_mma()
{
    extern __shared__ char sm[];
    char* sA_hi = sm;
    char* sA_lo = sm + 9216;
    char* sB_hi = sm + 18432;
    char* sB_lo = sm + 55296;

    const int t    = threadIdx.x;
    const int lane = t & 31;
    const int wid  = t >> 5;
    const int wm   = wid & 1;
    const int wn   = wid >> 1;
    const int m0   = blockIdx.x * 64;

    const unsigned lrow = (lane & 15);
    const unsigned lcol = (lane >> 4) << 4;
    const unsigned aBase0 = smem_u32(sA_hi) + (wm * 32 + lrow) * PITCHB + lcol;
    const unsigned bBase0 = smem_u32(sB_hi) + (wn * 64 + lrow) * PITCHB + lcol;

    float acc[2][8][4] = {};

    for (int kc = 0; kc < 4; kc++) {
        const int j0 = kc * 64;
        __syncthreads();
        #pragma unroll
        for (int q = 0; q < 2; q++) {
            const int idx = q * 256 + t;
            const int row = idx >> 3, seg = idx & 7;
            const size_t go = (size_t)(m0 + row) * DIM + j0 + seg * 8;
            const unsigned off = row * PITCHB + seg * 16;
            *(uint4*)(sA_hi + off) = *(const uint4*)(g_X_hi + go);
            *(uint4*)(sA_lo + off) = *(const uint4*)(g_X_lo + go);
        }
        #pragma unroll
        for (int q = 0; q < 8; q++) {
            const int idx = q * 256 + t;
            const int d = idx >> 3, seg = idx & 7;
            const size_t go = (size_t)d * DIM + j0 + seg * 8;
            const unsigned off = d * PITCHB + seg * 16;
            *(uint4*)(sB_hi + off) = *(const uint4*)(g_WT_hi + go);
            *(uint4*)(sB_lo + off) = *(const uint4*)(g_WT_lo + go);
        }
        __syncthreads();
        #pragma unroll
        for (int ks = 0; ks < 4; ks++) {
            unsigned ah[2][4], al[2][4];
            #pragma unroll
            for (int mt = 0; mt < 2; mt++) {
                ldsm_x4(ah[mt], aBase0 + mt * 16 * PITCHB + ks * 32);
                ldsm_x4(al[mt], aBase0 + 9216u + mt * 16 * PITCHB + ks * 32);
            }
            #pragma unroll
            for (int np = 0; np < 4; np++) {
                unsigned bh[4], bl[4];
                ldsm_x4(bh, bBase0 + np * 16 * PITCHB + ks * 32);
                ldsm_x4(bl, bBase0 + 36864u + np * 16 * PITCHB + ks * 32);
                #pragma unroll
                for (int mt = 0; mt < 2; mt++) {
                    mma_bf16(acc[mt][np*2+0], ah[mt], bh[0], bh[2]);
                    mma_bf16(acc[mt][np*2+1], ah[mt], bh[1], bh[3]);
                    mma_bf16(acc[mt][np*2+0], ah[mt], bl[0], bl[2]);
                    mma_bf16(acc[mt][np*2+1], ah[mt], bl[1], bl[3]);
                    mma_bf16(acc[mt][np*2+0], al[mt], bh[0], bh[2]);
                    mma_bf16(acc[mt][np*2+1], al[mt], bh[1], bh[3]);
                }
            }
        }
    }
    #pragma unroll
    for (int mt = 0; mt < 2; mt++) {
        const int row0 = m0 + wm * 32 + mt * 16 + (lane >> 2);
        #pragma unroll
        for (int nf = 0; nf < 8; nf++) {
            const int col = wn * 64 + nf * 8 + (lane & 3) * 2;
            *(float2*)(g_h + (size_t)row0 * DIM + col) =
                make_float2(acc[mt][nf][0], acc[mt][nf][1]);
            *(float2*)(g_h + (size_t)(row0 + 8) * DIM + col) =
                make_float2(acc[mt][nf][2], acc[mt][nf][3]);
        }
    }
}

// ---------------- K2: a_src / a_dst (warp per row, float4) ------------------
__global__ __launch_bounds__(256) void k2_coef(const float* __restrict__ Ws)
{
    const int lane = threadIdx.x & 31;
    const int row  = blockIdx.x * 8 + (threadIdx.x >> 5);
    const float* hr = g_h + (size_t)row * DIM + lane * 8;
    float4 h0 = *(const float4*)hr;
    float4 h1 = *(const float4*)(hr + 4);
    float4 s0 = *(const float4*)(Ws + lane * 8);
    float4 s1 = *(const float4*)(Ws + lane * 8 + 4);
    float4 d0 = *(const float4*)(Ws + DIM + lane * 8);
    float4 d1 = *(const float4*)(Ws + DIM + lane * 8 + 4);
    float ps = h0.x*s0.x + h0.y*s0.y + h0.z*s0.z + h0.w*s0.w
             + h1.x*s1.x + h1.y*s1.y + h1.z*s1.z + h1.w*s1.w;
    float pd = h0.x*d0.x + h0.y*d0.y + h0.z*d0.z + h0.w*d0.w
             + h1.x*d1.x + h1.y*d1.y + h1.z*d1.z + h1.w*d1.w;
    #pragma unroll
    for (int o = 16; o > 0; o >>= 1) {
        ps += __shfl_xor_sync(0xffffffffu, ps, o);
        pd += __shfl_xor_sync(0xffffffffu, pd, o);
    }
    if (lane == 0) { g_asrc[row] = ps; g_adst[row] = pd; }
}

// ---------------- K2b: transpose + fp16 split  h -> hT_hi/lo [b][d][j] ------
__global__ __launch_bounds__(256) void k2b_split()
{
    __shared__ float tile[32][33];
    const int b = blockIdx.z, j0 = blockIdx.x * 32, d0 = blockIdx.y * 32;
    const int c = threadIdx.x & 31, r0 = threadIdx.x >> 5;
    #pragma unroll
    for (int k = 0; k < 4; k++) {
        int r = r0 + k * 8;
        tile[r][c] = g_h[((size_t)(b * NSEQ + j0 + r)) * DIM + d0 + c];
    }
    __syncthreads();
    #pragma unroll
    for (int k = 0; k < 4; k++) {
        int r = r0 + k * 8;           // d offset within tile
        float v = tile[c][r];
        __half hb, lb;
        split_f16(v, hb, lb);
        size_t o = ((size_t)(b * DIM + d0 + r)) * NSEQ + j0 + c;
        g_hT_hi[o] = hb;
        g_hT_lo[o] = lb;
    }
}

// ---------------- K3: write I_A + full softmax P (single fp16) --------------
__global__ __launch_bounds__(256) void k3_ia_p(const int*   __restrict__ adj,
                                               const float* __restrict__ bsv,
                                               float*       __restrict__ outIA)
{
    const int i = blockIdx.x;
    const int b = blockIdx.y;
    const int t = threadIdx.x;
    const int lane = t & 31, warp = t >> 5;
    const int j0 = t * 8;
    const size_t rbase = ((size_t)b * NSEQ + i) * NSEQ;
    const float asrc = g_asrc[b * NSEQ + i];
    const float bs0  = bsv[0];

    int4 a0 = *(const int4*)(adj + rbase + j0);
    int4 a1 = *(const int4*)(adj + rbase + j0 + 4);
    const int av[8] = {a0.x, a0.y, a0.z, a0.w, a1.x, a1.y, a1.z, a1.w};
    float ad[8];
    *(float4*)(ad)     = *(const float4*)(g_adst + b * NSEQ + j0);
    *(float4*)(ad + 4) = *(const float4*)(g_adst + b * NSEQ + j0 + 4);

    float sc[8], iav[8];
    float mx = -3.0e38f;
    #pragma unroll
    for (int e = 0; e < 8; e++) {
        const int j = j0 + e;
        float x = asrc + ad[e] + bs0;
        float attn = (j < i) ? fsigmoid(x) : 0.0f;
        float ia = ((j == i) ? 1.0f : 0.0f) - attn;
        iav[e] = ia;
        float s = ((j <= i) && (av[e] == 1)) ? ia : NEGV;
        sc[e] = s;
        mx = fmaxf(mx, s);
    }
    *(float4*)(outIA + rbase + j0)     = *(float4*)(iav);
    *(float4*)(outIA + rbase + j0 + 4) = *(float4*)(iav + 4);

    __shared__ float redm[8], reds[8];
    #pragma unroll
    for (int o = 16; o > 0; o >>= 1) mx = fmaxf(mx, __shfl_xor_sync(0xffffffffu, mx, o));
    if (lane == 0) redm[warp] = mx;
    __syncthreads();
    float bm = redm[0];
    #pragma unroll
    for (int w = 1; w < 8; w++) bm = fmaxf(bm, redm[w]);

    float ex[8];
    float sum = 0.f;
    #pragma unroll
    for (int e = 0; e < 8; e++) { ex[e] = __expf(sc[e] - bm); sum += ex[e]; }
    #pragma unroll
    for (int o = 16; o > 0; o >>= 1) sum += __shfl_xor_sync(0xffffffffu, sum, o);
    if (lane == 0) reds[warp] = sum;
    __syncthreads();
    float tot = 0.f;
    #pragma unroll
    for (int w = 0; w < 8; w++) tot += reds[w];
    const float inv = __fdividef(1.0f, tot);

    union { __half h[8]; uint4 v; } Up;
    #pragma unroll
    for (int e = 0; e < 8; e++) Up.h[e] = __float2half_rn(ex[e] * inv);
    *(uint4*)(g_P + rbase + j0) = Up.v;
}

// ---------------- K4: feat_out = P @ h + b — fp16 2-product GEMM ------------
// CTA: M=128 (i), N=256 (d), K=2048 (32 chunks of 64). 512 threads = 16 warps
// (4m x 4n, warp tile m32 x n64). Double-buffered SMEM via cp.async.
// Buffer layout (92160 B each): A(P) @0 (18432), B_hi @18432 (36864), B_lo @55296.
#define KCH    64
#define BUF_SZ 92160u
__device__ __forceinline__ void k4_prefetch(int b, int i0, int j0, unsigned sb)
{
    const int t = threadIdx.x;
    #pragma unroll
    for (int q = 0; q < 2; q++) {
        const int idx = q * 512 + t;
        const int row = idx >> 3, seg = idx & 7;
        const size_t go = ((size_t)(b * NSEQ + i0 + row)) * NSEQ + j0 + seg * 8;
        cp_async16(sb + row * PITCHB + seg * 16, g_P + go);
    }
    #pragma unroll
    for (int q = 0; q < 4; q++) {
        const int idx = q * 512 + t;
        const int d = idx >> 3, seg = idx & 7;
        const size_t go = ((size_t)(b * DIM + d)) * NSEQ + j0 + seg * 8;
        const unsigned off = d * PITCHB + seg * 16;
        cp_async16(sb + 18432u + off, g_hT_hi + go);
        cp_async16(sb + 55296u + off, g_hT_lo + go);
    }
}

__global__ __launch_bounds__(512, 1) void k4_mma(const float* __restrict__ bias,
                                                 float*       __restrict__ outFO)
{
    extern __shared__ char sm[];
    const int t    = threadIdx.x;
    const int lane = t & 31;
    const int wid  = t >> 5;
    const int wm   = wid & 3;           // 4 m-warps -> 32 rows each
    const int wn   = wid >> 2;          // 4 n-warps -> 64 cols each
    const int b    = blockIdx.y;
    const int i0   = blockIdx.x * 128;

    const unsigned smb  = smem_u32(sm);
    const unsigned lrow = (lane & 15);
    const unsigned lcol = (lane >> 4) << 4;
    const unsigned aBase0 = smb + (wm * 32 + lrow) * PITCHB + lcol;            // A (P)
    const unsigned bBase0 = smb + 18432u + (wn * 64 + lrow) * PITCHB + lcol;   // B_hi

    float acc[2][8][4] = {};

    k4_prefetch(b, i0, 0, smb);
    CP_COMMIT();

    for (int c = 0; c < NSEQ / KCH; c++) {
        const unsigned bufOff = (c & 1) * BUF_SZ;
        if (c + 1 < NSEQ / KCH) {
            k4_prefetch(b, i0, (c + 1) * KCH, smb + ((c + 1) & 1) * BUF_SZ);
            CP_COMMIT();
            CP_WAIT(1);                    // chunk c resident
        } else {
            CP_WAIT(0);
        }
        __syncthreads();

        #pragma unroll
        for (int ks = 0; ks < 4; ks++) {
            unsigned ah[2][4];
            #pragma unroll
            for (int mt = 0; mt < 2; mt++)
                ldsm_x4(ah[mt], aBase0 + bufOff + mt * 16 * PITCHB + ks * 32);
            #pragma unroll
            for (int np = 0; np < 4; np++) {
                unsigned bh[4], bl[4];
                ldsm_x4(bh, bBase0 + bufOff + np * 16 * PITCHB + ks * 32);
                ldsm_x4(bl, bBase0 + bufOff + 36864u + np * 16 * PITCHB + ks * 32);
                #pragma unroll
                for (int mt = 0; mt < 2; mt++) {
                    mma_f16(acc[mt][np*2+0], ah[mt], bh[0], bh[2]);   // P * h_hi
                    mma_f16(acc[mt][np*2+1], ah[mt], bh[1], bh[3]);
                    mma_f16(acc[mt][np*2+0], ah[mt], bl[0], bl[2]);   // P * h_lo
                    mma_f16(acc[mt][np*2+1], ah[mt], bl[1], bl[3]);
                }
            }
        }
        __syncthreads();                  // mma(c) done before buf overwrite
    }

    // ---- epilogue: accum + bias -> outFO ----
    #pragma unroll
    for (int mt = 0; mt < 2; mt++) {
        const int row0 = i0 + wm * 32 + mt * 16 + (lane >> 2);
        #pragma unroll
        for (int nf = 0; nf < 8; nf++) {
            const int col = wn * 64 + nf * 8 + (lane & 3) * 2;
            const float b0 = bias[col], b1 = bias[col + 1];
            float2 v0 = make_float2(acc[mt][nf][0] + b0, acc[mt][nf][1] + b1);
            float2 v1 = make_float2(acc[mt][nf][2] + b0, acc[mt][nf][3] + b1);
            *(float2*)(outFO + ((size_t)(b * NSEQ + row0)) * DIM + col) = v0;
            *(float2*)(outFO + ((size_t)(b * NSEQ + row0 + 8)) * DIM + col) = v1;
        }
    }
}

// ---------------- K5: gate = sigmoid(X@Hw^T+Hb), blend, via mma.sync --------
__global__ __launch_bounds__(256, 2) void k5_mma(const float* __restrict__ X,
                                                 const float* __restrict__ Hb,
                                                 float*       __restrict__ out)
{
    extern __shared__ char sm[];
    char* sA_hi = sm;
    char* sA_lo = sm + 9216;
    char* sB_hi = sm + 18432;
    char* sB_lo = sm + 55296;

    const int t    = threadIdx.x;
    const int lane = t & 31;
    const int wid  = t >> 5;
    const int wm   = wid & 1;
    const int wn   = wid >> 1;
    const int m0   = blockIdx.x * 64;

    const unsigned lrow = (lane & 15);
    const unsigned lcol = (lane >> 4) << 4;
    const unsigned aBase0 = smem_u32(sA_hi) + (wm * 32 + lrow) * PITCHB + lcol;
    const unsigned bBase0 = smem_u32(sB_hi) + (wn * 64 + lrow) * PITCHB + lcol;

    float acc[2][8][4] = {};

    for (int kc = 0; kc < 4; kc++) {
        const int j0 = kc * 64;
        __syncthreads();
        #pragma unroll
        for (int q = 0; q < 2; q++) {
            const int idx = q * 256 + t;
            const int row = idx >> 3, seg = idx & 7;
            const size_t go = (size_t)(m0 + row) * DIM + j0 + seg * 8;
            const unsigned off = row * PITCHB + seg * 16;
            *(uint4*)(sA_hi + off) = *(const uint4*)(g_X_hi + go);
            *(uint4*)(sA_lo + off) = *(const uint4*)(g_X_lo + go);
        }
        #pragma unroll
        for (int q = 0; q < 8; q++) {
            const int idx = q * 256 + t;
            const int d = idx >> 3, seg = idx & 7;
            const size_t go = (size_t)d * DIM + j0 + seg * 8;
            const unsigned off = d * PITCHB + seg * 16;
            *(uint4*)(sB_hi + off) = *(const uint4*)(g_Hw_hi + go);
            *(uint4*)(sB_lo + off) = *(const uint4*)(g_Hw_lo + go);
        }
        __syncthreads();
        #pragma unroll
        for (int ks = 0; ks < 4; ks++) {
            unsigned ah[2][4], al[2][4];
            #pragma unroll
            for (int mt = 0; mt < 2; mt++) {
                ldsm_x4(ah[mt], aBase0 + mt * 16 * PITCHB + ks * 32);
                ldsm_x4(al[mt], aBase0 + 9216u + mt * 16 * PITCHB + ks * 32);
            }
            #pragma unroll
            for (int np = 0; np < 4; np++) {
                unsigned bh[4], bl[4];
                ldsm_x4(bh, bBase0 + np * 16 * PITCHB + ks * 32);
                ldsm_x4(bl, bBase0 + 36864u + np * 16 * PITCHB + ks * 32);
                #pragma unroll
                for (int mt = 0; mt < 2; mt++) {
                    mma_bf16(acc[mt][np*2+0], ah[mt], bh[0], bh[2]);
                    mma_bf16(acc[mt][np*2+1], ah[mt], bh[1], bh[3]);
                    mma_bf16(acc[mt][np*2+0], ah[mt], bl[0], bl[2]);
                    mma_bf16(acc[mt][np*2+1], ah[mt], bl[1], bl[3]);
                    mma_bf16(acc[mt][np*2+0], al[mt], bh[0], bh[2]);
                    mma_bf16(acc[mt][np*2+1], al[mt], bh[1], bh[3]);
                }
            }
        }
    }

    // epilogue: gate + elu + blend (out holds feat_out pre-activation)
    #pragma unroll
    for (int mt = 0; mt < 2; mt++) {
        const int row0 = m0 + wm * 32 + mt * 16 + (lane >> 2);
        #pragma unroll
        for (int nf = 0; nf < 8; nf++) {
            const int col = wn * 64 + nf * 8 + (lane & 3) * 2;
            const float hb0 = Hb[col], hb1 = Hb[col + 1];
            #pragma unroll
            for (int rr = 0; rr < 2; rr++) {
                const size_t o = (size_t)(row0 + rr * 8) * DIM + col;
                float2 fo = *(const float2*)(out + o);
                float2 xv = *(const float2*)(X + o);
                float g0 = fsigmoid(acc[mt][nf][rr*2+0] + hb0);
                float g1 = fsigmoid(acc[mt][nf][rr*2+1] + hb1);
                float e0 = (fo.x > 0.0f) ? fo.x : expm1f(fo.x);
                float e1 = (fo.y > 0.0f) ? fo.y : expm1f(fo.y);
                float2 r;
                r.x = g0 * e0 + (1.0f - g0) * xv.x;
                r.y = g1 * e1 + (1.0f - g1) * xv.y;
                *(float2*)(out + o) = r;
            }
        }
    }
}

// ---------------- launch ----------------------------------------------------
extern "C" void kernel_launch(void* const* d_in, const int* in_sizes, int n_in,
                              void* d_out, int out_size)
{
    const float* feat = (const float*)d_in[0];
    const int*   adj  = (const int*)  d_in[1];
    const float* W    = (const float*)d_in[2];
    const float* bvec = (const float*)d_in[3];
    const float* Ws   = (const float*)d_in[4];
    const float* bs   = (const float*)d_in[5];
    const float* Hw   = (const float*)d_in[6];
    const float* Hb   = (const float*)d_in[7];

    float* out   = (float*)d_out;                      // (B,N,256)
    float* outIA = out + (size_t)NROWS * DIM;          // (B,1,N,N)

    cudaFuncSetAttribute(k1_mma, cudaFuncAttributeMaxDynamicSharedMemorySize, 92160);
    cudaFuncSetAttribute(k4_mma, cudaFuncAttributeMaxDynamicSharedMemorySize, 2 * BUF_SZ);
    cudaFuncSetAttribute(k5_mma, cudaFuncAttributeMaxDynamicSharedMemorySize, 92160);

    k0a_splitX<<<NROWS * DIM / 1024, 256>>>(feat);
    k0b_splitW<<<DIM, DIM>>>(W, Hw);
    k1_mma   <<<NROWS / 64, 256, 92160>>>();
    k2_coef  <<<NROWS / 8, 256>>>(Ws);
    k2b_split<<<dim3(NSEQ / 32, DIM / 32, BATCH), 256>>>();
    k3_ia_p  <<<dim3(NSEQ, BATCH), 256>>>(adj, bs, outIA);
    k4_mma   <<<dim3(NSEQ / 128, BATCH), 512, 2 * BUF_SZ>>>(bvec, out);
    k5_mma   <<<NROWS / 64, 256, 92160>>>(feat, Hb, out);
}

// round 11
// speedup vs baseline: 2.4629x; 1.2739x over previous
#include <cuda_runtime.h>
#include <cuda_bf16.h>
#include <cuda_fp16.h>

#define BATCH 8
#define NSEQ  2048
#define DIM   256
#define NROWS (BATCH * NSEQ)          // 16384
#define NEGV  (-999999.0f)

// ---------------- scratch (device globals; no allocation allowed) ----------
__device__ float g_h[(size_t)NROWS * DIM];              // h = X @ W   (16.8 MB)
__device__ __half g_hT[(size_t)NROWS * DIM];            // h^T fp16 [b][d][j]
__device__ __nv_bfloat16 g_X_hi[(size_t)NROWS * DIM];   // feat split  [m][k]
__device__ __nv_bfloat16 g_X_lo[(size_t)NROWS * DIM];
__device__ __nv_bfloat16 g_WT_hi[DIM * DIM];            // W^T split   [n][k]
__device__ __nv_bfloat16 g_WT_lo[DIM * DIM];
__device__ __nv_bfloat16 g_Hw_hi[DIM * DIM];            // Hw split    [n][k]
__device__ __nv_bfloat16 g_Hw_lo[DIM * DIM];
__device__ __half g_P[(size_t)NROWS * NSEQ];            // softmax P fp16 (67MB)
__device__ float g_asrc[NROWS];
__device__ float g_adst[NROWS];

__device__ __forceinline__ float fsigmoid(float x) {
    return __fdividef(1.0f, 1.0f + __expf(-x));
}

__device__ __forceinline__ unsigned smem_u32(const void* p) {
    unsigned a;
    asm("{ .reg .u64 t; cvta.to.shared.u64 t, %1; cvt.u32.u64 %0, t; }"
        : "=r"(a) : "l"(p));
    return a;
}

__device__ __forceinline__ void ldsm_x4(unsigned r[4], unsigned addr) {
    asm volatile("ldmatrix.sync.aligned.m8n8.x4.shared.b16 {%0,%1,%2,%3}, [%4];"
                 : "=r"(r[0]), "=r"(r[1]), "=r"(r[2]), "=r"(r[3]) : "r"(addr));
}

__device__ __forceinline__ void mma_bf16(float c[4], const unsigned a[4],
                                         unsigned b0, unsigned b1) {
    asm volatile("mma.sync.aligned.m16n8k16.row.col.f32.bf16.bf16.f32 "
                 "{%0,%1,%2,%3}, {%4,%5,%6,%7}, {%8,%9}, {%0,%1,%2,%3};"
                 : "+f"(c[0]), "+f"(c[1]), "+f"(c[2]), "+f"(c[3])
                 : "r"(a[0]), "r"(a[1]), "r"(a[2]), "r"(a[3]), "r"(b0), "r"(b1));
}

__device__ __forceinline__ void mma_f16(float c[4], const unsigned a[4],
                                        unsigned b0, unsigned b1) {
    asm volatile("mma.sync.aligned.m16n8k16.row.col.f32.f16.f16.f32 "
                 "{%0,%1,%2,%3}, {%4,%5,%6,%7}, {%8,%9}, {%0,%1,%2,%3};"
                 : "+f"(c[0]), "+f"(c[1]), "+f"(c[2]), "+f"(c[3])
                 : "r"(a[0]), "r"(a[1]), "r"(a[2]), "r"(a[3]), "r"(b0), "r"(b1));
}

__device__ __forceinline__ void split_bf16(float v, __nv_bfloat16& hi, __nv_bfloat16& lo) {
    hi = __float2bfloat16_rn(v);
    lo = __float2bfloat16_rn(v - __bfloat162float(hi));
}

__device__ __forceinline__ void cp_async16(unsigned saddr, const void* gptr) {
    asm volatile("cp.async.cg.shared.global [%0], [%1], 16;"
                 :: "r"(saddr), "l"(gptr) : "memory");
}
#define CP_COMMIT() asm volatile("cp.async.commit_group;" ::: "memory")
#define CP_WAIT(N)  asm volatile("cp.async.wait_group %0;" :: "n"(N) : "memory")

#define PITCHB 144

// ---------------- K0a: split X (feat) into bf16 hi/lo -----------------------
__global__ __launch_bounds__(256) void k0a_splitX(const float* __restrict__ X)
{
    const size_t base = (size_t)blockIdx.x * 1024 + threadIdx.x * 4;
    float4 v = *(const float4*)(X + base);
    union { __nv_bfloat16 h[4]; uint2 u; } Uh, Ul;
    split_bf16(v.x, Uh.h[0], Ul.h[0]);
    split_bf16(v.y, Uh.h[1], Ul.h[1]);
    split_bf16(v.z, Uh.h[2], Ul.h[2]);
    split_bf16(v.w, Uh.h[3], Ul.h[3]);
    *(uint2*)(g_X_hi + base) = Uh.u;
    *(uint2*)(g_X_lo + base) = Ul.u;
}

// ---------------- K0b: W^T split + Hw split ---------------------------------
__global__ __launch_bounds__(256) void k0b_splitW(const float* __restrict__ W,
                                                  const float* __restrict__ Hw)
{
    const int n = blockIdx.x;            // 0..255
    const int k = threadIdx.x;           // 0..255
    split_bf16(W[k * DIM + n], g_WT_hi[n * DIM + k], g_WT_lo[n * DIM + k]);
    split_bf16(Hw[n * DIM + k], g_Hw_hi[n * DIM + k], g_Hw_lo[n * DIM + k]);
}

// ---------------- K1: h = X @ W via mma.sync bf16 split ---------------------
__global__ __launch_bounds__(256, 2) void k1_mma()
{
    extern __shared__ char sm[];
    char* sA_hi = sm;
    char* sA_lo = sm + 9216;
    char* sB_hi = sm + 18432;
    char* sB_lo = sm + 55296;

    const int t    = threadIdx.x;
    const int lane = t & 31;
    const int wid  = t >> 5;
    const int wm   = wid & 1;
    const int wn   = wid >> 1;
    const int m0   = blockIdx.x * 64;

    const unsigned lrow = (lane & 15);
    const unsigned lcol = (lane >> 4) << 4;
    const unsigned aBase0 = smem_u32(sA_hi) + (wm * 32 + lrow) * PITCHB + lcol;
    const unsigned bBase0 = smem_u32(sB_hi) + (wn * 64 + lrow) * PITCHB + lcol;

    float acc[2][8][4] = {};

    for (int kc = 0; kc < 4; kc++) {
        const int j0 = kc * 64;
        __syncthreads();
        #pragma unroll
        for (int q = 0; q < 2; q++) {
            const int idx = q * 256 + t;
            const int row = idx >> 3, seg = idx & 7;
            const size_t go = (size_t)(m0 + row) * DIM + j0 + seg * 8;
            const unsigned off = row * PITCHB + seg * 16;
            *(uint4*)(sA_hi + off) = *(const uint4*)(g_X_hi + go);
            *(uint4*)(sA_lo + off) = *(const uint4*)(g_X_lo + go);
        }
        #pragma unroll
        for (int q = 0; q < 8; q++) {
            const int idx = q * 256 + t;
            const int d = idx >> 3, seg = idx & 7;
            const size_t go = (size_t)d * DIM + j0 + seg * 8;
            const unsigned off = d * PITCHB + seg * 16;
            *(uint4*)(sB_hi + off) = *(const uint4*)(g_WT_hi + go);
            *(uint4*)(sB_lo + off) = *(const uint4*)(g_WT_lo + go);
        }
        __syncthreads();
        #pragma unroll
        for (int ks = 0; ks < 4; ks++) {
            unsigned ah[2][4], al[2][4];
            #pragma unroll
            for (int mt = 0; mt < 2; mt++) {
                ldsm_x4(ah[mt], aBase0 + mt * 16 * PITCHB + ks * 32);
                ldsm_x4(al[mt], aBase0 + 9216u + mt * 16 * PITCHB + ks * 32);
            }
            #pragma unroll
            for (int np = 0; np < 4; np++) {
                unsigned bh[4], bl[4];
                ldsm_x4(bh, bBase0 + np * 16 * PITCHB + ks * 32);
                ldsm_x4(bl, bBase0 + 36864u + np * 16 * PITCHB + ks * 32);
                #pragma unroll
                for (int mt = 0; mt < 2; mt++) {
                    mma_bf16(acc[mt][np*2+0], ah[mt], bh[0], bh[2]);
                    mma_bf16(acc[mt][np*2+1], ah[mt], bh[1], bh[3]);
                    mma_bf16(acc[mt][np*2+0], ah[mt], bl[0], bl[2]);
                    mma_bf16(acc[mt][np*2+1], ah[mt], bl[1], bl[3]);
                    mma_bf16(acc[mt][np*2+0], al[mt], bh[0], bh[2]);
                    mma_bf16(acc[mt][np*2+1], al[mt], bh[1], bh[3]);
                }
            }
        }
    }
    #pragma unroll
    for (int mt = 0; mt < 2; mt++) {
        const int row0 = m0 + wm * 32 + mt * 16 + (lane >> 2);
        #pragma unroll
        for (int nf = 0; nf < 8; nf++) {
            const int col = wn * 64 + nf * 8 + (lane & 3) * 2;
            *(float2*)(g_h + (size_t)row0 * DIM + col) =
                make_float2(acc[mt][nf][0], acc[mt][nf][1]);
            *(float2*)(g_h + (size_t)(row0 + 8) * DIM + col) =
                make_float2(acc[mt][nf][2], acc[mt][nf][3]);
        }
    }
}

// ---------------- K2: a_src / a_dst (warp per row, float4) ------------------
__global__ __launch_bounds__(256) void k2_coef(const float* __restrict__ Ws)
{
    const int lane = threadIdx.x & 31;
    const int row  = blockIdx.x * 8 + (threadIdx.x >> 5);
    const float* hr = g_h + (size_t)row * DIM + lane * 8;
    float4 h0 = *(const float4*)hr;
    float4 h1 = *(const float4*)(hr + 4);
    float4 s0 = *(const float4*)(Ws + lane * 8);
    float4 s1 = *(const float4*)(Ws + lane * 8 + 4);
    float4 d0 = *(const float4*)(Ws + DIM + lane * 8);
    float4 d1 = *(const float4*)(Ws + DIM + lane * 8 + 4);
    float ps = h0.x*s0.x + h0.y*s0.y + h0.z*s0.z + h0.w*s0.w
             + h1.x*s1.x + h1.y*s1.y + h1.z*s1.z + h1.w*s1.w;
    float pd = h0.x*d0.x + h0.y*d0.y + h0.z*d0.z + h0.w*d0.w
             + h1.x*d1.x + h1.y*d1.y + h1.z*d1.z + h1.w*d1.w;
    #pragma unroll
    for (int o = 16; o > 0; o >>= 1) {
        ps += __shfl_xor_sync(0xffffffffu, ps, o);
        pd += __shfl_xor_sync(0xffffffffu, pd, o);
    }
    if (lane == 0) { g_asrc[row] = ps; g_adst[row] = pd; }
}

// ---------------- K2b: transpose + fp16 cast  h -> hT [b][d][j] -------------
__global__ __launch_bounds__(256) void k2b_split()
{
    __shared__ float tile[32][33];
    const int b = blockIdx.z, j0 = blockIdx.x * 32, d0 = blockIdx.y * 32;
    const int c = threadIdx.x & 31, r0 = threadIdx.x >> 5;
    #pragma unroll
    for (int k = 0; k < 4; k++) {
        int r = r0 + k * 8;
        tile[r][c] = g_h[((size_t)(b * NSEQ + j0 + r)) * DIM + d0 + c];
    }
    __syncthreads();
    #pragma unroll
    for (int k = 0; k < 4; k++) {
        int r = r0 + k * 8;           // d offset within tile
        g_hT[((size_t)(b * DIM + d0 + r)) * NSEQ + j0 + c] =
            __float2half_rn(tile[c][r]);
    }
}

// ---------------- K3: write I_A + full softmax P (single fp16) --------------
__global__ __launch_bounds__(256) void k3_ia_p(const int*   __restrict__ adj,
                                               const float* __restrict__ bsv,
                                               float*       __restrict__ outIA)
{
    const int i = blockIdx.x;
    const int b = blockIdx.y;
    const int t = threadIdx.x;
    const int lane = t & 31, warp = t >> 5;
    const int j0 = t * 8;
    const size_t rbase = ((size_t)b * NSEQ + i) * NSEQ;
    const float asrc = g_asrc[b * NSEQ + i];
    const float bs0  = bsv[0];

    int4 a0 = *(const int4*)(adj + rbase + j0);
    int4 a1 = *(const int4*)(adj + rbase + j0 + 4);
    const int av[8] = {a0.x, a0.y, a0.z, a0.w, a1.x, a1.y, a1.z, a1.w};
    float ad[8];
    *(float4*)(ad)     = *(const float4*)(g_adst + b * NSEQ + j0);
    *(float4*)(ad + 4) = *(const float4*)(g_adst + b * NSEQ + j0 + 4);

    float sc[8], iav[8];
    float mx = -3.0e38f;
    #pragma unroll
    for (int e = 0; e < 8; e++) {
        const int j = j0 + e;
        float x = asrc + ad[e] + bs0;
        float attn = (j < i) ? fsigmoid(x) : 0.0f;
        float ia = ((j == i) ? 1.0f : 0.0f) - attn;
        iav[e] = ia;
        float s = ((j <= i) && (av[e] == 1)) ? ia : NEGV;
        sc[e] = s;
        mx = fmaxf(mx, s);
    }
    *(float4*)(outIA + rbase + j0)     = *(float4*)(iav);
    *(float4*)(outIA + rbase + j0 + 4) = *(float4*)(iav + 4);

    __shared__ float redm[8], reds[8];
    #pragma unroll
    for (int o = 16; o > 0; o >>= 1) mx = fmaxf(mx, __shfl_xor_sync(0xffffffffu, mx, o));
    if (lane == 0) redm[warp] = mx;
    __syncthreads();
    float bm = redm[0];
    #pragma unroll
    for (int w = 1; w < 8; w++) bm = fmaxf(bm, redm[w]);

    float ex[8];
    float sum = 0.f;
    #pragma unroll
    for (int e = 0; e < 8; e++) { ex[e] = __expf(sc[e] - bm); sum += ex[e]; }
    #pragma unroll
    for (int o = 16; o > 0; o >>= 1) sum += __shfl_xor_sync(0xffffffffu, sum, o);
    if (lane == 0) reds[warp] = sum;
    __syncthreads();
    float tot = 0.f;
    #pragma unroll
    for (int w = 0; w < 8; w++) tot += reds[w];
    const float inv = __fdividef(1.0f, tot);

    union { __half h[8]; uint4 v; } Up;
    #pragma unroll
    for (int e = 0; e < 8; e++) Up.h[e] = __float2half_rn(ex[e] * inv);
    *(uint4*)(g_P + rbase + j0) = Up.v;
}

// ---------------- K4: feat_out = P @ h + b — single fp16 product GEMM -------
// CTA: M=128 (i), N=256 (d), K=2048 (32 chunks of 64). 512 threads = 16 warps
// (4m x 4n, warp tile m32 x n64). Double-buffered SMEM via cp.async.
// Buffer layout (55296 B each): A(P) @0 (18432), B(hT) @18432 (36864).
#define KCH    64
#define BUF_SZ 55296u
__device__ __forceinline__ void k4_prefetch(int b, int i0, int j0, unsigned sb)
{
    const int t = threadIdx.x;
    #pragma unroll
    for (int q = 0; q < 2; q++) {
        const int idx = q * 512 + t;
        const int row = idx >> 3, seg = idx & 7;
        const size_t go = ((size_t)(b * NSEQ + i0 + row)) * NSEQ + j0 + seg * 8;
        cp_async16(sb + row * PITCHB + seg * 16, g_P + go);
    }
    #pragma unroll
    for (int q = 0; q < 4; q++) {
        const int idx = q * 512 + t;
        const int d = idx >> 3, seg = idx & 7;
        const size_t go = ((size_t)(b * DIM + d)) * NSEQ + j0 + seg * 8;
        cp_async16(sb + 18432u + d * PITCHB + seg * 16, g_hT + go);
    }
}

__global__ __launch_bounds__(512, 1) void k4_mma(const float* __restrict__ bias,
                                                 float*       __restrict__ outFO)
{
    extern __shared__ char sm[];
    const int t    = threadIdx.x;
    const int lane = t & 31;
    const int wid  = t >> 5;
    const int wm   = wid & 3;           // 4 m-warps -> 32 rows each
    const int wn   = wid >> 2;          // 4 n-warps -> 64 cols each
    const int b    = blockIdx.y;
    const int i0   = blockIdx.x * 128;

    const unsigned smb  = smem_u32(sm);
    const unsigned lrow = (lane & 15);
    const unsigned lcol = (lane >> 4) << 4;
    const unsigned aBase0 = smb + (wm * 32 + lrow) * PITCHB + lcol;            // A (P)
    const unsigned bBase0 = smb + 18432u + (wn * 64 + lrow) * PITCHB + lcol;   // B (hT)

    float acc[2][8][4] = {};

    k4_prefetch(b, i0, 0, smb);
    CP_COMMIT();

    for (int c = 0; c < NSEQ / KCH; c++) {
        const unsigned bufOff = (c & 1) * BUF_SZ;
        if (c + 1 < NSEQ / KCH) {
            k4_prefetch(b, i0, (c + 1) * KCH, smb + ((c + 1) & 1) * BUF_SZ);
            CP_COMMIT();
            CP_WAIT(1);                    // chunk c resident
        } else {
            CP_WAIT(0);
        }
        __syncthreads();

        #pragma unroll
        for (int ks = 0; ks < 4; ks++) {
            unsigned ah[2][4];
            #pragma unroll
            for (int mt = 0; mt < 2; mt++)
                ldsm_x4(ah[mt], aBase0 + bufOff + mt * 16 * PITCHB + ks * 32);
            #pragma unroll
            for (int np = 0; np < 4; np++) {
                unsigned bh[4];
                ldsm_x4(bh, bBase0 + bufOff + np * 16 * PITCHB + ks * 32);
                #pragma unroll
                for (int mt = 0; mt < 2; mt++) {
                    mma_f16(acc[mt][np*2+0], ah[mt], bh[0], bh[2]);   // P * h
                    mma_f16(acc[mt][np*2+1], ah[mt], bh[1], bh[3]);
                }
            }
        }
        __syncthreads();                  // mma(c) done before buf overwrite
    }

    // ---- epilogue: accum + bias -> outFO ----
    #pragma unroll
    for (int mt = 0; mt < 2; mt++) {
        const int row0 = i0 + wm * 32 + mt * 16 + (lane >> 2);
        #pragma unroll
        for (int nf = 0; nf < 8; nf++) {
            const int col = wn * 64 + nf * 8 + (lane & 3) * 2;
            const float b0 = bias[col], b1 = bias[col + 1];
            float2 v0 = make_float2(acc[mt][nf][0] + b0, acc[mt][nf][1] + b1);
            float2 v1 = make_float2(acc[mt][nf][2] + b0, acc[mt][nf][3] + b1);
            *(float2*)(outFO + ((size_t)(b * NSEQ + row0)) * DIM + col) = v0;
            *(float2*)(outFO + ((size_t)(b * NSEQ + row0 + 8)) * DIM + col) = v1;
        }
    }
}

// ---------------- K5: gate = sigmoid(X@Hw^T+Hb), blend, via mma.sync --------
__global__ __launch_bounds__(256, 2) void k5_mma(const float* __restrict__ X,
                                                 const float* __restrict__ Hb,
                                                 float*       __restrict__ out)
{
    extern __shared__ char sm[];
    char* sA_hi = sm;
    char* sA_lo = sm + 9216;
    char* sB_hi = sm + 18432;
    char* sB_lo = sm + 55296;

    const int t    = threadIdx.x;
    const int lane = t & 31;
    const int wid  = t >> 5;
    const int wm   = wid & 1;
    const int wn   = wid >> 1;
    const int m0   = blockIdx.x * 64;

    const unsigned lrow = (lane & 15);
    const unsigned lcol = (lane >> 4) << 4;
    const unsigned aBase0 = smem_u32(sA_hi) + (wm * 32 + lrow) * PITCHB + lcol;
    const unsigned bBase0 = smem_u32(sB_hi) + (wn * 64 + lrow) * PITCHB + lcol;

    float acc[2][8][4] = {};

    for (int kc = 0; kc < 4; kc++) {
        const int j0 = kc * 64;
        __syncthreads();
        #pragma unroll
        for (int q = 0; q < 2; q++) {
            const int idx = q * 256 + t;
            const int row = idx >> 3, seg = idx & 7;
            const size_t go = (size_t)(m0 + row) * DIM + j0 + seg * 8;
            const unsigned off = row * PITCHB + seg * 16;
            *(uint4*)(sA_hi + off) = *(const uint4*)(g_X_hi + go);
            *(uint4*)(sA_lo + off) = *(const uint4*)(g_X_lo + go);
        }
        #pragma unroll
        for (int q = 0; q < 8; q++) {
            const int idx = q * 256 + t;
            const int d = idx >> 3, seg = idx & 7;
            const size_t go = (size_t)d * DIM + j0 + seg * 8;
            const unsigned off = d * PITCHB + seg * 16;
            *(uint4*)(sB_hi + off) = *(const uint4*)(g_Hw_hi + go);
            *(uint4*)(sB_lo + off) = *(const uint4*)(g_Hw_lo + go);
        }
        __syncthreads();
        #pragma unroll
        for (int ks = 0; ks < 4; ks++) {
            unsigned ah[2][4], al[2][4];
            #pragma unroll
            for (int mt = 0; mt < 2; mt++) {
                ldsm_x4(ah[mt], aBase0 + mt * 16 * PITCHB + ks * 32);
                ldsm_x4(al[mt], aBase0 + 9216u + mt * 16 * PITCHB + ks * 32);
            }
            #pragma unroll
            for (int np = 0; np < 4; np++) {
                unsigned bh[4], bl[4];
                ldsm_x4(bh, bBase0 + np * 16 * PITCHB + ks * 32);
                ldsm_x4(bl, bBase0 + 36864u + np * 16 * PITCHB + ks * 32);
                #pragma unroll
                for (int mt = 0; mt < 2; mt++) {
                    mma_bf16(acc[mt][np*2+0], ah[mt], bh[0], bh[2]);
                    mma_bf16(acc[mt][np*2+1], ah[mt], bh[1], bh[3]);
                    mma_bf16(acc[mt][np*2+0], ah[mt], bl[0], bl[2]);
                    mma_bf16(acc[mt][np*2+1], ah[mt], bl[1], bl[3]);
                    mma_bf16(acc[mt][np*2+0], al[mt], bh[0], bh[2]);
                    mma_bf16(acc[mt][np*2+1], al[mt], bh[1], bh[3]);
                }
            }
        }
    }

    // epilogue: gate + elu + blend (out holds feat_out pre-activation)
    #pragma unroll
    for (int mt = 0; mt < 2; mt++) {
        const int row0 = m0 + wm * 32 + mt * 16 + (lane >> 2);
        #pragma unroll
        for (int nf = 0; nf < 8; nf++) {
            const int col = wn * 64 + nf * 8 + (lane & 3) * 2;
            const float hb0 = Hb[col], hb1 = Hb[col + 1];
            #pragma unroll
            for (int rr = 0; rr < 2; rr++) {
                const size_t o = (size_t)(row0 + rr * 8) * DIM + col;
                float2 fo = *(const float2*)(out + o);
                float2 xv = *(const float2*)(X + o);
                float g0 = fsigmoid(acc[mt][nf][rr*2+0] + hb0);
                float g1 = fsigmoid(acc[mt][nf][rr*2+1] + hb1);
                float e0 = (fo.x > 0.0f) ? fo.x : expm1f(fo.x);
                float e1 = (fo.y > 0.0f) ? fo.y : expm1f(fo.y);
                float2 r;
                r.x = g0 * e0 + (1.0f - g0) * xv.x;
                r.y = g1 * e1 + (1.0f - g1) * xv.y;
                *(float2*)(out + o) = r;
            }
        }
    }
}

// ---------------- launch ----------------------------------------------------
extern "C" void kernel_launch(void* const* d_in, const int* in_sizes, int n_in,
                              void* d_out, int out_size)
{
    const float* feat = (const float*)d_in[0];
    const int*   adj  = (const int*)  d_in[1];
    const float* W    = (const float*)d_in[2];
    const float* bvec = (const float*)d_in[3];
    const float* Ws   = (const float*)d_in[4];
    const float* bs   = (const float*)d_in[5];
    const float* Hw   = (const float*)d_in[6];
    const float* Hb   = (const float*)d_in[7];

    float* out   = (float*)d_out;                      // (B,N,256)
    float* outIA = out + (size_t)NROWS * DIM;          // (B,1,N,N)

    cudaFuncSetAttribute(k1_mma, cudaFuncAttributeMaxDynamicSharedMemorySize, 92160);
    cudaFuncSetAttribute(k4_mma, cudaFuncAttributeMaxDynamicSharedMemorySize, 2 * BUF_SZ);
    cudaFuncSetAttribute(k5_mma, cudaFuncAttributeMaxDynamicSharedMemorySize, 92160);

    k0a_splitX<<<NROWS * DIM / 1024, 256>>>(feat);
    k0b_splitW<<<DIM, DIM>>>(W, Hw);
    k1_mma   <<<NROWS / 64, 256, 92160>>>();
    k2_coef  <<<NROWS / 8, 256>>>(Ws);
    k2b_split<<<dim3(NSEQ / 32, DIM / 32, BATCH), 256>>>();
    k3_ia_p  <<<dim3(NSEQ, BATCH), 256>>>(adj, bs, outIA);
    k4_mma   <<<dim3(NSEQ / 128, BATCH), 512, 2 * BUF_SZ>>>(bvec, out);
    k5_mma   <<<NROWS / 64, 256, 92160>>>(feat, Hb, out);
}

// round 12
// speedup vs baseline: 2.6809x; 1.0885x over previous
#include <cuda_runtime.h>
#include <cuda_bf16.h>
#include <cuda_fp16.h>

#define BATCH 8
#define NSEQ  2048
#define DIM   256
#define NROWS (BATCH * NSEQ)          // 16384
#define NEGV  (-999999.0f)

// ---------------- scratch (device globals; no allocation allowed) ----------
__device__ __half g_hT[(size_t)NROWS * DIM];            // h^T fp16 [b][d][j]
__device__ __nv_bfloat16 g_WT_hi[DIM * DIM];            // W^T split   [n][k]
__device__ __nv_bfloat16 g_WT_lo[DIM * DIM];
__device__ __nv_bfloat16 g_Hw_hi[DIM * DIM];            // Hw split    [n][k]
__device__ __nv_bfloat16 g_Hw_lo[DIM * DIM];
__device__ __half g_P[(size_t)NROWS * NSEQ];            // softmax P fp16 (67MB)
__device__ float g_asrc[NROWS];
__device__ float g_adst[NROWS];

__device__ __forceinline__ float fsigmoid(float x) {
    return __fdividef(1.0f, 1.0f + __expf(-x));
}

__device__ __forceinline__ unsigned smem_u32(const void* p) {
    unsigned a;
    asm("{ .reg .u64 t; cvta.to.shared.u64 t, %1; cvt.u32.u64 %0, t; }"
        : "=r"(a) : "l"(p));
    return a;
}

__device__ __forceinline__ void ldsm_x4(unsigned r[4], unsigned addr) {
    asm volatile("ldmatrix.sync.aligned.m8n8.x4.shared.b16 {%0,%1,%2,%3}, [%4];"
                 : "=r"(r[0]), "=r"(r[1]), "=r"(r[2]), "=r"(r[3]) : "r"(addr));
}

__device__ __forceinline__ void mma_bf16(float c[4], const unsigned a[4],
                                         unsigned b0, unsigned b1) {
    asm volatile("mma.sync.aligned.m16n8k16.row.col.f32.bf16.bf16.f32 "
                 "{%0,%1,%2,%3}, {%4,%5,%6,%7}, {%8,%9}, {%0,%1,%2,%3};"
                 : "+f"(c[0]), "+f"(c[1]), "+f"(c[2]), "+f"(c[3])
                 : "r"(a[0]), "r"(a[1]), "r"(a[2]), "r"(a[3]), "r"(b0), "r"(b1));
}

__device__ __forceinline__ void mma_f16(float c[4], const unsigned a[4],
                                        unsigned b0, unsigned b1) {
    asm volatile("mma.sync.aligned.m16n8k16.row.col.f32.f16.f16.f32 "
                 "{%0,%1,%2,%3}, {%4,%5,%6,%7}, {%8,%9}, {%0,%1,%2,%3};"
                 : "+f"(c[0]), "+f"(c[1]), "+f"(c[2]), "+f"(c[3])
                 : "r"(a[0]), "r"(a[1]), "r"(a[2]), "r"(a[3]), "r"(b0), "r"(b1));
}

__device__ __forceinline__ void split_bf16(float v, __nv_bfloat16& hi, __nv_bfloat16& lo) {
    hi = __float2bfloat16_rn(v);
    lo = __float2bfloat16_rn(v - __bfloat162float(hi));
}

__device__ __forceinline__ void cp_async16(unsigned saddr, const void* gptr) {
    asm volatile("cp.async.cg.shared.global [%0], [%1], 16;"
                 :: "r"(saddr), "l"(gptr) : "memory");
}
#define CP_COMMIT() asm volatile("cp.async.commit_group;" ::: "memory")
#define CP_WAIT(N)  asm volatile("cp.async.wait_group %0;" :: "n"(N) : "memory")

#define PITCHB 144

// ---------------- K0b: W^T split + Hw split ---------------------------------
__global__ __launch_bounds__(256) void k0b_splitW(const float* __restrict__ W,
                                                  const float* __restrict__ Hw)
{
    const int n = blockIdx.x;            // 0..255
    const int k = threadIdx.x;           // 0..255
    split_bf16(W[k * DIM + n], g_WT_hi[n * DIM + k], g_WT_lo[n * DIM + k]);
    split_bf16(Hw[n * DIM + k], g_Hw_hi[n * DIM + k], g_Hw_lo[n * DIM + k]);
}

// ---------------- K1: h = X @ W (bf16-split mma) + fused epilogue -----------
// Epilogue: (a) a_src/a_dst via smem reduction (CTA owns full 256-col width),
//           (b) h -> fp16 transposed to g_hT via smem staging.
// g_h (fp32) is never materialized.
__global__ __launch_bounds__(256, 2) void k1_mma(const float* __restrict__ X,
                                                 const float* __restrict__ Ws)
{
    extern __shared__ char sm[];
    char* sA_hi = sm;
    char* sA_lo = sm + 9216;
    char* sB_hi = sm + 18432;
    char* sB_lo = sm + 55296;
    __shared__ float s_ws[2][DIM];

    const int t    = threadIdx.x;
    const int lane = t & 31;
    const int wid  = t >> 5;
    const int wm   = wid & 1;
    const int wn   = wid >> 1;
    const int m0   = blockIdx.x * 64;

    s_ws[0][t] = Ws[t];
    s_ws[1][t] = Ws[DIM + t];

    const unsigned lrow = (lane & 15);
    const unsigned lcol = (lane >> 4) << 4;
    const unsigned aBase0 = smem_u32(sA_hi) + (wm * 32 + lrow) * PITCHB + lcol;
    const unsigned bBase0 = smem_u32(sB_hi) + (wn * 64 + lrow) * PITCHB + lcol;

    float acc[2][8][4] = {};

    for (int kc = 0; kc < 4; kc++) {
        const int j0 = kc * 64;
        __syncthreads();
        // A tile 64x64: read X fp32, split bf16 hi/lo on the fly
        #pragma unroll
        for (int q = 0; q < 2; q++) {
            const int idx = q * 256 + t;
            const int row = idx >> 3, seg = idx & 7;
            const float* gx = X + (size_t)(m0 + row) * DIM + j0 + seg * 8;
            float4 v0 = *(const float4*)gx;
            float4 v1 = *(const float4*)(gx + 4);
            union { __nv_bfloat16 h[8]; uint4 v; } Uh, Ul;
            split_bf16(v0.x, Uh.h[0], Ul.h[0]);
            split_bf16(v0.y, Uh.h[1], Ul.h[1]);
            split_bf16(v0.z, Uh.h[2], Ul.h[2]);
            split_bf16(v0.w, Uh.h[3], Ul.h[3]);
            split_bf16(v1.x, Uh.h[4], Ul.h[4]);
            split_bf16(v1.y, Uh.h[5], Ul.h[5]);
            split_bf16(v1.z, Uh.h[6], Ul.h[6]);
            split_bf16(v1.w, Uh.h[7], Ul.h[7]);
            const unsigned off = row * PITCHB + seg * 16;
            *(uint4*)(sA_hi + off) = Uh.v;
            *(uint4*)(sA_lo + off) = Ul.v;
        }
        // B tile 256x64 from pre-split W^T
        #pragma unroll
        for (int q = 0; q < 8; q++) {
            const int idx = q * 256 + t;
            const int d = idx >> 3, seg = idx & 7;
            const size_t go = (size_t)d * DIM + j0 + seg * 8;
            const unsigned off = d * PITCHB + seg * 16;
            *(uint4*)(sB_hi + off) = *(const uint4*)(g_WT_hi + go);
            *(uint4*)(sB_lo + off) = *(const uint4*)(g_WT_lo + go);
        }
        __syncthreads();
        #pragma unroll
        for (int ks = 0; ks < 4; ks++) {
            unsigned ah[2][4], al[2][4];
            #pragma unroll
            for (int mt = 0; mt < 2; mt++) {
                ldsm_x4(ah[mt], aBase0 + mt * 16 * PITCHB + ks * 32);
                ldsm_x4(al[mt], aBase0 + 9216u + mt * 16 * PITCHB + ks * 32);
            }
            #pragma unroll
            for (int np = 0; np < 4; np++) {
                unsigned bh[4], bl[4];
                ldsm_x4(bh, bBase0 + np * 16 * PITCHB + ks * 32);
                ldsm_x4(bl, bBase0 + 36864u + np * 16 * PITCHB + ks * 32);
                #pragma unroll
                for (int mt = 0; mt < 2; mt++) {
                    mma_bf16(acc[mt][np*2+0], ah[mt], bh[0], bh[2]);
                    mma_bf16(acc[mt][np*2+1], ah[mt], bh[1], bh[3]);
                    mma_bf16(acc[mt][np*2+0], ah[mt], bl[0], bl[2]);
                    mma_bf16(acc[mt][np*2+1], ah[mt], bl[1], bl[3]);
                    mma_bf16(acc[mt][np*2+0], al[mt], bh[0], bh[2]);
                    mma_bf16(acc[mt][np*2+1], al[mt], bh[1], bh[3]);
                }
            }
        }
    }

    // ---- fused epilogue ----
    __syncthreads();                          // mainloop smem free
    __half* smT   = (__half*)sm;              // [col][row], pitch 72 halves (36864B)
    float* partS  = (float*)(sm + 36864);     // [64][16] (4096B)
    float* partD  = (float*)(sm + 40960);     // [64][16] (4096B)

    float ps[2][2] = {}, pd[2][2] = {};
    #pragma unroll
    for (int mt = 0; mt < 2; mt++) {
        const int rA = wm * 32 + mt * 16 + (lane >> 2);
        const int rB = rA + 8;
        #pragma unroll
        for (int nf = 0; nf < 8; nf++) {
            const int c0 = wn * 64 + nf * 8 + (lane & 3) * 2;
            smT[(c0    ) * 72 + rA] = __float2half_rn(acc[mt][nf][0]);
            smT[(c0 + 1) * 72 + rA] = __float2half_rn(acc[mt][nf][1]);
            smT[(c0    ) * 72 + rB] = __float2half_rn(acc[mt][nf][2]);
            smT[(c0 + 1) * 72 + rB] = __float2half_rn(acc[mt][nf][3]);
            ps[mt][0] += acc[mt][nf][0] * s_ws[0][c0] + acc[mt][nf][1] * s_ws[0][c0 + 1];
            pd[mt][0] += acc[mt][nf][0] * s_ws[1][c0] + acc[mt][nf][1] * s_ws[1][c0 + 1];
            ps[mt][1] += acc[mt][nf][2] * s_ws[0][c0] + acc[mt][nf][3] * s_ws[0][c0 + 1];
            pd[mt][1] += acc[mt][nf][2] * s_ws[1][c0] + acc[mt][nf][3] * s_ws[1][c0 + 1];
        }
        const int slot = wn * 4 + (lane & 3);
        partS[rA * 16 + slot] = ps[mt][0];
        partD[rA * 16 + slot] = pd[mt][0];
        partS[rB * 16 + slot] = ps[mt][1];
        partD[rB * 16 + slot] = pd[mt][1];
    }
    __syncthreads();

    // coalesced copy-out of transposed fp16 h
    {
        const int b  = m0 >> 11;
        const int j0 = m0 & 2047;
        const int colg = t >> 3, seg = t & 7;
        #pragma unroll
        for (int k = 0; k < 8; k++) {
            const int col = colg + k * 32;
            uint4 v = *(const uint4*)((const char*)smT + col * 144 + seg * 16);
            *(uint4*)(g_hT + ((size_t)(b * DIM + col)) * NSEQ + j0 + seg * 8) = v;
        }
    }
    // final a_src/a_dst reduction
    if (t < 64) {
        float s = 0.f, d = 0.f;
        #pragma unroll
        for (int k = 0; k < 16; k++) { s += partS[t * 16 + k]; d += partD[t * 16 + k]; }
        g_asrc[m0 + t] = s;
        g_adst[m0 + t] = d;
    }
}

// ---------------- K3: write I_A + full softmax P (single fp16) --------------
__global__ __launch_bounds__(256) void k3_ia_p(const int*   __restrict__ adj,
                                               const float* __restrict__ bsv,
                                               float*       __restrict__ outIA)
{
    const int i = blockIdx.x;
    const int b = blockIdx.y;
    const int t = threadIdx.x;
    const int lane = t & 31, warp = t >> 5;
    const int j0 = t * 8;
    const size_t rbase = ((size_t)b * NSEQ + i) * NSEQ;
    const float asrc = g_asrc[b * NSEQ + i];
    const float bs0  = bsv[0];

    int4 a0 = *(const int4*)(adj + rbase + j0);
    int4 a1 = *(const int4*)(adj + rbase + j0 + 4);
    const int av[8] = {a0.x, a0.y, a0.z, a0.w, a1.x, a1.y, a1.z, a1.w};
    float ad[8];
    *(float4*)(ad)     = *(const float4*)(g_adst + b * NSEQ + j0);
    *(float4*)(ad + 4) = *(const float4*)(g_adst + b * NSEQ + j0 + 4);

    float sc[8], iav[8];
    float mx = -3.0e38f;
    #pragma unroll
    for (int e = 0; e < 8; e++) {
        const int j = j0 + e;
        float x = asrc + ad[e] + bs0;
        float attn = (j < i) ? fsigmoid(x) : 0.0f;
        float ia = ((j == i) ? 1.0f : 0.0f) - attn;
        iav[e] = ia;
        float s = ((j <= i) && (av[e] == 1)) ? ia : NEGV;
        sc[e] = s;
        mx = fmaxf(mx, s);
    }
    *(float4*)(outIA + rbase + j0)     = *(float4*)(iav);
    *(float4*)(outIA + rbase + j0 + 4) = *(float4*)(iav + 4);

    __shared__ float redm[8], reds[8];
    #pragma unroll
    for (int o = 16; o > 0; o >>= 1) mx = fmaxf(mx, __shfl_xor_sync(0xffffffffu, mx, o));
    if (lane == 0) redm[warp] = mx;
    __syncthreads();
    float bm = redm[0];
    #pragma unroll
    for (int w = 1; w < 8; w++) bm = fmaxf(bm, redm[w]);

    float ex[8];
    float sum = 0.f;
    #pragma unroll
    for (int e = 0; e < 8; e++) { ex[e] = __expf(sc[e] - bm); sum += ex[e]; }
    #pragma unroll
    for (int o = 16; o > 0; o >>= 1) sum += __shfl_xor_sync(0xffffffffu, sum, o);
    if (lane == 0) reds[warp] = sum;
    __syncthreads();
    float tot = 0.f;
    #pragma unroll
    for (int w = 0; w < 8; w++) tot += reds[w];
    const float inv = __fdividef(1.0f, tot);

    union { __half h[8]; uint4 v; } Up;
    #pragma unroll
    for (int e = 0; e < 8; e++) Up.h[e] = __float2half_rn(ex[e] * inv);
    *(uint4*)(g_P + rbase + j0) = Up.v;
}

// ---------------- K4: feat_out = P @ h + b — single fp16 product GEMM -------
#define KCH    64
#define BUF_SZ 55296u
__device__ __forceinline__ void k4_prefetch(int b, int i0, int j0, unsigned sb)
{
    const int t = threadIdx.x;
    #pragma unroll
    for (int q = 0; q < 2; q++) {
        const int idx = q * 512 + t;
        const int row = idx >> 3, seg = idx & 7;
        const size_t go = ((size_t)(b * NSEQ + i0 + row)) * NSEQ + j0 + seg * 8;
        cp_async16(sb + row * PITCHB + seg * 16, g_P + go);
    }
    #pragma unroll
    for (int q = 0; q < 4; q++) {
        const int idx = q * 512 + t;
        const int d = idx >> 3, seg = idx & 7;
        const size_t go = ((size_t)(b * DIM + d)) * NSEQ + j0 + seg * 8;
        cp_async16(sb + 18432u + d * PITCHB + seg * 16, g_hT + go);
    }
}

__global__ __launch_bounds__(512, 1) void k4_mma(const float* __restrict__ bias,
                                                 float*       __restrict__ outFO)
{
    extern __shared__ char sm[];
    const int t    = threadIdx.x;
    const int lane = t & 31;
    const int wid  = t >> 5;
    const int wm   = wid & 3;
    const int wn   = wid >> 2;
    const int b    = blockIdx.y;
    const int i0   = blockIdx.x * 128;

    const unsigned smb  = smem_u32(sm);
    const unsigned lrow = (lane & 15);
    const unsigned lcol = (lane >> 4) << 4;
    const unsigned aBase0 = smb + (wm * 32 + lrow) * PITCHB + lcol;
    const unsigned bBase0 = smb + 18432u + (wn * 64 + lrow) * PITCHB + lcol;

    float acc[2][8][4] = {};

    k4_prefetch(b, i0, 0, smb);
    CP_COMMIT();

    for (int c = 0; c < NSEQ / KCH; c++) {
        const unsigned bufOff = (c & 1) * BUF_SZ;
        if (c + 1 < NSEQ / KCH) {
            k4_prefetch(b, i0, (c + 1) * KCH, smb + ((c + 1) & 1) * BUF_SZ);
            CP_COMMIT();
            CP_WAIT(1);
        } else {
            CP_WAIT(0);
        }
        __syncthreads();

        #pragma unroll
        for (int ks = 0; ks < 4; ks++) {
            unsigned ah[2][4];
            #pragma unroll
            for (int mt = 0; mt < 2; mt++)
                ldsm_x4(ah[mt], aBase0 + bufOff + mt * 16 * PITCHB + ks * 32);
            #pragma unroll
            for (int np = 0; np < 4; np++) {
                unsigned bh[4];
                ldsm_x4(bh, bBase0 + bufOff + np * 16 * PITCHB + ks * 32);
                #pragma unroll
                for (int mt = 0; mt < 2; mt++) {
                    mma_f16(acc[mt][np*2+0], ah[mt], bh[0], bh[2]);
                    mma_f16(acc[mt][np*2+1], ah[mt], bh[1], bh[3]);
                }
            }
        }
        __syncthreads();
    }

    #pragma unroll
    for (int mt = 0; mt < 2; mt++) {
        const int row0 = i0 + wm * 32 + mt * 16 + (lane >> 2);
        #pragma unroll
        for (int nf = 0; nf < 8; nf++) {
            const int col = wn * 64 + nf * 8 + (lane & 3) * 2;
            const float b0 = bias[col], b1 = bias[col + 1];
            float2 v0 = make_float2(acc[mt][nf][0] + b0, acc[mt][nf][1] + b1);
            float2 v1 = make_float2(acc[mt][nf][2] + b0, acc[mt][nf][3] + b1);
            *(float2*)(outFO + ((size_t)(b * NSEQ + row0)) * DIM + col) = v0;
            *(float2*)(outFO + ((size_t)(b * NSEQ + row0 + 8)) * DIM + col) = v1;
        }
    }
}

// ---------------- K5: gate = sigmoid(X@Hw^T+Hb), blend, via mma.sync --------
__global__ __launch_bounds__(256, 2) void k5_mma(const float* __restrict__ X,
                                                 const float* __restrict__ Hb,
                                                 float*       __restrict__ out)
{
    extern __shared__ char sm[];
    char* sA_hi = sm;
    char* sA_lo = sm + 9216;
    char* sB_hi = sm + 18432;
    char* sB_lo = sm + 55296;

    const int t    = threadIdx.x;
    const int lane = t & 31;
    const int wid  = t >> 5;
    const int wm   = wid & 1;
    const int wn   = wid >> 1;
    const int m0   = blockIdx.x * 64;

    const unsigned lrow = (lane & 15);
    const unsigned lcol = (lane >> 4) << 4;
    const unsigned aBase0 = smem_u32(sA_hi) + (wm * 32 + lrow) * PITCHB + lcol;
    const unsigned bBase0 = smem_u32(sB_hi) + (wn * 64 + lrow) * PITCHB + lcol;

    float acc[2][8][4] = {};

    for (int kc = 0; kc < 4; kc++) {
        const int j0 = kc * 64;
        __syncthreads();
        #pragma unroll
        for (int q = 0; q < 2; q++) {
            const int idx = q * 256 + t;
            const int row = idx >> 3, seg = idx & 7;
            const float* gx = X + (size_t)(m0 + row) * DIM + j0 + seg * 8;
            float4 v0 = *(const float4*)gx;
            float4 v1 = *(const float4*)(gx + 4);
            union { __nv_bfloat16 h[8]; uint4 v; } Uh, Ul;
            split_bf16(v0.x, Uh.h[0], Ul.h[0]);
            split_bf16(v0.y, Uh.h[1], Ul.h[1]);
            split_bf16(v0.z, Uh.h[2], Ul.h[2]);
            split_bf16(v0.w, Uh.h[3], Ul.h[3]);
            split_bf16(v1.x, Uh.h[4], Ul.h[4]);
            split_bf16(v1.y, Uh.h[5], Ul.h[5]);
            split_bf16(v1.z, Uh.h[6], Ul.h[6]);
            split_bf16(v1.w, Uh.h[7], Ul.h[7]);
            const unsigned off = row * PITCHB + seg * 16;
            *(uint4*)(sA_hi + off) = Uh.v;
            *(uint4*)(sA_lo + off) = Ul.v;
        }
        #pragma unroll
        for (int q = 0; q < 8; q++) {
            const int idx = q * 256 + t;
            const int d = idx >> 3, seg = idx & 7;
            const size_t go = (size_t)d * DIM + j0 + seg * 8;
            const unsigned off = d * PITCHB + seg * 16;
            *(uint4*)(sB_hi + off) = *(const uint4*)(g_Hw_hi + go);
            *(uint4*)(sB_lo + off) = *(const uint4*)(g_Hw_lo + go);
        }
        __syncthreads();
        #pragma unroll
        for (int ks = 0; ks < 4; ks++) {
            unsigned ah[2][4], al[2][4];
            #pragma unroll
            for (int mt = 0; mt < 2; mt++) {
                ldsm_x4(ah[mt], aBase0 + mt * 16 * PITCHB + ks * 32);
                ldsm_x4(al[mt], aBase0 + 9216u + mt * 16 * PITCHB + ks * 32);
            }
            #pragma unroll
            for (int np = 0; np < 4; np++) {
                unsigned bh[4], bl[4];
                ldsm_x4(bh, bBase0 + np * 16 * PITCHB + ks * 32);
                ldsm_x4(bl, bBase0 + 36864u + np * 16 * PITCHB + ks * 32);
                #pragma unroll
                for (int mt = 0; mt < 2; mt++) {
                    mma_bf16(acc[mt][np*2+0], ah[mt], bh[0], bh[2]);
                    mma_bf16(acc[mt][np*2+1], ah[mt], bh[1], bh[3]);
                    mma_bf16(acc[mt][np*2+0], ah[mt], bl[0], bl[2]);
                    mma_bf16(acc[mt][np*2+1], ah[mt], bl[1], bl[3]);
                    mma_bf16(acc[mt][np*2+0], al[mt], bh[0], bh[2]);
                    mma_bf16(acc[mt][np*2+1], al[mt], bh[1], bh[3]);
                }
            }
        }
    }

    // epilogue: gate + elu + blend (out holds feat_out pre-activation)
    #pragma unroll
    for (int mt = 0; mt < 2; mt++) {
        const int row0 = m0 + wm * 32 + mt * 16 + (lane >> 2);
        #pragma unroll
        for (int nf = 0; nf < 8; nf++) {
            const int col = wn * 64 + nf * 8 + (lane & 3) * 2;
            const float hb0 = Hb[col], hb1 = Hb[col + 1];
            #pragma unroll
            for (int rr = 0; rr < 2; rr++) {
                const size_t o = (size_t)(row0 + rr * 8) * DIM + col;
                float2 fo = *(const float2*)(out + o);
                float2 xv = *(const float2*)(X + o);
                float g0 = fsigmoid(acc[mt][nf][rr*2+0] + hb0);
                float g1 = fsigmoid(acc[mt][nf][rr*2+1] + hb1);
                float e0 = (fo.x > 0.0f) ? fo.x : expm1f(fo.x);
                float e1 = (fo.y > 0.0f) ? fo.y : expm1f(fo.y);
                float2 r;
                r.x = g0 * e0 + (1.0f - g0) * xv.x;
                r.y = g1 * e1 + (1.0f - g1) * xv.y;
                *(float2*)(out + o) = r;
            }
        }
    }
}

// ---------------- launch ----------------------------------------------------
extern "C" void kernel_launch(void* const* d_in, const int* in_sizes, int n_in,
                              void* d_out, int out_size)
{
    const float* feat = (const float*)d_in[0];
    const int*   adj  = (const int*)  d_in[1];
    const float* W    = (const float*)d_in[2];
    const float* bvec = (const float*)d_in[3];
    const float* Ws   = (const float*)d_in[4];
    const float* bs   = (const float*)d_in[5];
    const float* Hw   = (const float*)d_in[6];
    const float* Hb   = (const float*)d_in[7];

    float* out   = (float*)d_out;                      // (B,N,256)
    float* outIA = out + (size_t)NROWS * DIM;          // (B,1,N,N)

    cudaFuncSetAttribute(k1_mma, cudaFuncAttributeMaxDynamicSharedMemorySize, 92160);
    cudaFuncSetAttribute(k4_mma, cudaFuncAttributeMaxDynamicSharedMemorySize, 2 * BUF_SZ);
    cudaFuncSetAttribute(k5_mma, cudaFuncAttributeMaxDynamicSharedMemorySize, 92160);

    k0b_splitW<<<DIM, DIM>>>(W, Hw);
    k1_mma   <<<NROWS / 64, 256, 92160>>>(feat, Ws);
    k3_ia_p  <<<dim3(NSEQ, BATCH), 256>>>(adj, bs, outIA);
    k4_mma   <<<dim3(NSEQ / 128, BATCH), 512, 2 * BUF_SZ>>>(bvec, out);
    k5_mma   <<<NROWS / 64, 256, 92160>>>(feat, Hb, out);
}